// round 2
// baseline (speedup 1.0000x reference)
#include <cuda_runtime.h>

// Problem constants (fixed shapes)
namespace {
constexpr int Bn = 8;
constexpr int Sn = 1024;
constexpr int Dn = 512;
constexpr int Hn = 8;
constexpr int DHn = 64;
constexpr int Mproj = Bn * Sn;           // 8192
constexpr long long HEAD_ELEMS = (long long)Bn * Hn * Sn * DHn;   // 4M complex
constexpr long long S_ELEMS    = (long long)Bn * Hn * Sn * Sn;    // 64M complex

// Scratch (device globals; allocation-free per harness rules)
__device__ float2 g_q[HEAD_ELEMS];   // [B,H,S,DH] complex
__device__ float2 g_k[HEAD_ELEMS];
__device__ float2 g_v[HEAD_ELEMS];
__device__ float2 g_o[(long long)Bn * Sn * Dn];  // [B,S,D] complex (attn out)
__device__ float2 g_s[S_ELEMS];      // [B*H, S, S] complex scores/probs (512MB)
}

// ---------------------------------------------------------------------------
// Generic tiled complex GEMM: C[m,n] = alpha * sum_k A[m,k] * B[n_or_k,...]
// Block tile 64x64, per-thread 4x4 complex, k-step 16.
// BMODE: 0 = B from two real arrays (wr, wi), NT (B rows are [N,K])
//        1 = B complex interleaved, NT  ([N,K])
//        2 = B complex interleaved, NN  ([K,N])
// CMODE: 0 = plain: idx = z*strideC + m*ldc + n
//        1 = head-split store: [B,H,S,DH] from (m=(b,s), n=(h,dh))
//        2 = PV store: [B,S,D] from (z=(b,h), m=q, n=dh)
// ---------------------------------------------------------------------------
template<int BMODE, int CMODE>
__global__ void __launch_bounds__(256)
cgemm_kernel(const float2* __restrict__ A, int lda, long long strideA,
             const float2* __restrict__ Bc, int ldb, long long strideB,
             const float* __restrict__ Br, const float* __restrict__ Bi,
             float2* __restrict__ C, int ldc, long long strideC,
             int K, float alpha)
{
    __shared__ float2 As[16][65];   // padded: conflict-free LDS.64/STS.64
    __shared__ float2 Bs[16][65];

    const int tid = threadIdx.x;
    const int tx = tid & 15;
    const int ty = tid >> 4;
    const int z  = blockIdx.z;
    const int m0 = blockIdx.y * 64;
    const int n0 = blockIdx.x * 64;

    const float2* Ab = A + (long long)z * strideA + (long long)m0 * lda;
    const float2* Bb = (BMODE != 0) ? (Bc + (long long)z * strideB) : nullptr;

    float2 acc[4][4];
#pragma unroll
    for (int i = 0; i < 4; i++)
#pragma unroll
        for (int j = 0; j < 4; j++) acc[i][j] = make_float2(0.f, 0.f);

    const int r = tid >> 4;   // 0..15
    const int c = tid & 15;   // 0..15

    for (int k0 = 0; k0 < K; k0 += 16) {
        // --- load A tile (64 rows x 16 k), transpose into As[k][m] ---
#pragma unroll
        for (int q = 0; q < 4; q++)
            As[c][r + 16 * q] = Ab[(long long)(r + 16 * q) * lda + (k0 + c)];

        // --- load B tile into Bs[k][n] ---
        if (BMODE == 0) {
#pragma unroll
            for (int q = 0; q < 4; q++) {
                long long idx = (long long)(n0 + r + 16 * q) * ldb + (k0 + c);
                Bs[c][r + 16 * q] = make_float2(Br[idx], Bi[idx]);
            }
        } else if (BMODE == 1) {
#pragma unroll
            for (int q = 0; q < 4; q++)
                Bs[c][r + 16 * q] = Bb[(long long)(n0 + r + 16 * q) * ldb + (k0 + c)];
        } else {
            const int kk = tid >> 6;   // 0..3
            const int nn = tid & 63;   // 0..63
#pragma unroll
            for (int q = 0; q < 4; q++)
                Bs[kk + 4 * q][nn] = Bb[(long long)(k0 + kk + 4 * q) * ldb + (n0 + nn)];
        }
        __syncthreads();

        // --- FFMA inner loop: 16k x 16 complex MACs per thread ---
#pragma unroll
        for (int kk = 0; kk < 16; kk++) {
            float2 a[4], b[4];
#pragma unroll
            for (int i = 0; i < 4; i++) a[i] = As[kk][ty + 16 * i];
#pragma unroll
            for (int j = 0; j < 4; j++) b[j] = Bs[kk][tx + 16 * j];
#pragma unroll
            for (int i = 0; i < 4; i++)
#pragma unroll
                for (int j = 0; j < 4; j++) {
                    acc[i][j].x = fmaf(a[i].x, b[j].x, acc[i][j].x);
                    acc[i][j].x = fmaf(-a[i].y, b[j].y, acc[i][j].x);
                    acc[i][j].y = fmaf(a[i].x, b[j].y, acc[i][j].y);
                    acc[i][j].y = fmaf(a[i].y, b[j].x, acc[i][j].y);
                }
        }
        __syncthreads();
    }

    // --- epilogue ---
#pragma unroll
    for (int i = 0; i < 4; i++) {
        const int m = m0 + ty + 16 * i;
#pragma unroll
        for (int j = 0; j < 4; j++) {
            const int n = n0 + tx + 16 * j;
            const float2 v = make_float2(acc[i][j].x * alpha, acc[i][j].y * alpha);
            long long idx;
            if (CMODE == 0) {
                idx = (long long)z * strideC + (long long)m * ldc + n;
            } else if (CMODE == 1) {
                // [B,H,S,DH]: b = m/S, s = m%S, h = n/DH, dh = n%DH
                idx = ((long long)((m >> 10) * Hn + (n >> 6))) * (Sn * DHn)
                      + (long long)(m & (Sn - 1)) * DHn + (n & (DHn - 1));
            } else {
                // [B,S,D]: z = b*H + h, m = q, n = dh
                idx = (long long)(z >> 3) * ((long long)Sn * Dn)
                      + (long long)(z & 7) * DHn
                      + (long long)m * Dn + n;
            }
            C[idx] = v;
        }
    }
}

// ---------------------------------------------------------------------------
// Row softmax (in place) over last dim, real & imag components independently.
// One block per (b,h,q) row; float2 loads keep access fully coalesced.
// ---------------------------------------------------------------------------
__global__ void __launch_bounds__(256)
softmax_kernel(float2* __restrict__ s)
{
    float2* p = s + (long long)blockIdx.x * Sn;
    const int tid = threadIdx.x;

    float2 v[4];
    float mx = -1e30f, my = -1e30f;
#pragma unroll
    for (int q = 0; q < 4; q++) {
        v[q] = p[tid + 256 * q];
        mx = fmaxf(mx, v[q].x);
        my = fmaxf(my, v[q].y);
    }

    __shared__ float red0[8], red1[8];
#pragma unroll
    for (int o = 16; o > 0; o >>= 1) {
        mx = fmaxf(mx, __shfl_xor_sync(0xffffffffu, mx, o));
        my = fmaxf(my, __shfl_xor_sync(0xffffffffu, my, o));
    }
    const int wid = tid >> 5, lane = tid & 31;
    if (lane == 0) { red0[wid] = mx; red1[wid] = my; }
    __syncthreads();
    mx = red0[0]; my = red1[0];
#pragma unroll
    for (int w = 1; w < 8; w++) { mx = fmaxf(mx, red0[w]); my = fmaxf(my, red1[w]); }

    float sx = 0.f, sy = 0.f;
#pragma unroll
    for (int q = 0; q < 4; q++) {
        v[q].x = __expf(v[q].x - mx);
        v[q].y = __expf(v[q].y - my);
        sx += v[q].x; sy += v[q].y;
    }
#pragma unroll
    for (int o = 16; o > 0; o >>= 1) {
        sx += __shfl_xor_sync(0xffffffffu, sx, o);
        sy += __shfl_xor_sync(0xffffffffu, sy, o);
    }
    __syncthreads();  // all reads of red done before overwrite
    if (lane == 0) { red0[wid] = sx; red1[wid] = sy; }
    __syncthreads();
    sx = 0.f; sy = 0.f;
#pragma unroll
    for (int w = 0; w < 8; w++) { sx += red0[w]; sy += red1[w]; }
    const float rx = 1.f / sx, ry = 1.f / sy;
#pragma unroll
    for (int q = 0; q < 4; q++)
        p[tid + 256 * q] = make_float2(v[q].x * rx, v[q].y * ry);
}

// ---------------------------------------------------------------------------
extern "C" void kernel_launch(void* const* d_in, const int* in_sizes, int n_in,
                              void* d_out, int out_size)
{
    (void)in_sizes; (void)n_in; (void)out_size;
    const float2* Qin = (const float2*)d_in[0];
    const float2* Kin = (const float2*)d_in[1];
    const float2* Vin = (const float2*)d_in[2];
    const float* wq_r = (const float*)d_in[3];
    const float* wq_i = (const float*)d_in[4];
    const float* wk_r = (const float*)d_in[5];
    const float* wk_i = (const float*)d_in[6];
    const float* wv_r = (const float*)d_in[7];
    const float* wv_i = (const float*)d_in[8];
    const float* wo_r = (const float*)d_in[9];
    const float* wo_i = (const float*)d_in[10];

    float2 *q, *k, *v, *o, *s;
    cudaGetSymbolAddress((void**)&q, g_q);
    cudaGetSymbolAddress((void**)&k, g_k);
    cudaGetSymbolAddress((void**)&v, g_v);
    cudaGetSymbolAddress((void**)&o, g_o);
    cudaGetSymbolAddress((void**)&s, g_s);

    const dim3 blk(256);
    const dim3 gproj(Dn / 64, Mproj / 64, 1);          // (8, 128)
    const dim3 gsc(Sn / 64, Sn / 64, Bn * Hn);         // (16, 16, 64)
    const dim3 gpv(DHn / 64, Sn / 64, Bn * Hn);        // (1, 16, 64)

    const float scale = 0.125f;  // 1/sqrt(DH)

    // Q/K/V complex projections -> head-split layout [B,H,S,DH]
    // NOTE: ldb = Dn (weights are [D,D]); R1 bug was ldb=0 here.
    cgemm_kernel<0, 1><<<gproj, blk>>>(Qin, Dn, 0, nullptr, Dn, 0, wq_r, wq_i,
                                       q, 0, 0, Dn, 1.f);
    cgemm_kernel<0, 1><<<gproj, blk>>>(Kin, Dn, 0, nullptr, Dn, 0, wk_r, wk_i,
                                       k, 0, 0, Dn, 1.f);
    cgemm_kernel<0, 1><<<gproj, blk>>>(Vin, Dn, 0, nullptr, Dn, 0, wv_r, wv_i,
                                       v, 0, 0, Dn, 1.f);

    // Complex scores: S = scale * Q K^T   (batched over B*H)
    cgemm_kernel<1, 0><<<gsc, blk>>>(q, DHn, (long long)Sn * DHn,
                                     k, DHn, (long long)Sn * DHn,
                                     nullptr, nullptr,
                                     s, Sn, (long long)Sn * Sn, DHn, scale);

    // Component-wise softmax on real & imag planes
    softmax_kernel<<<Bn * Hn * Sn, 256>>>(s);

    // Complex PV: O = A V   (NN), store into [B,S,D]
    cgemm_kernel<2, 2><<<gpv, blk>>>(s, Sn, (long long)Sn * Sn,
                                     v, DHn, (long long)Sn * DHn,
                                     nullptr, nullptr,
                                     o, 0, 0, Sn, 1.f);

    // Output complex projection -> d_out [B,S,D,2]
    cgemm_kernel<0, 0><<<gproj, blk>>>(o, Dn, 0, nullptr, Dn, 0, wo_r, wo_i,
                                       (float2*)d_out, Dn, 0, Dn, 1.f);
}

// round 4
// speedup vs baseline: 1.3167x; 1.3167x over previous
#include <cuda_runtime.h>
#include <cuda_bf16.h>
#include <cstdint>

// ============================================================================
// Problem constants
// ============================================================================
namespace {
constexpr int Bn = 8;
constexpr int Sn = 1024;
constexpr int Dn = 512;
constexpr int Hn = 8;
constexpr int DHn = 64;
constexpr int Mproj = Bn * Sn;                                   // 8192
constexpr long long HEAD_ELEMS = (long long)Bn * Hn * Sn * DHn;  // 4M
constexpr long long S_ELEMS    = (long long)Bn * Hn * Sn * Sn;   // 64M complex

// Scratch (device globals; allocation-free per harness rules)
__device__ float g_qr[HEAD_ELEMS], g_qi[HEAD_ELEMS];
__device__ float g_kr[HEAD_ELEMS], g_ki[HEAD_ELEMS];
__device__ float g_vr[HEAD_ELEMS], g_vi[HEAD_ELEMS];
__device__ float2 g_o[(long long)Bn * Sn * Dn];    // attn out [B,S,D] complex
__device__ float2 g_s[S_ELEMS];                    // scores/probs (512MB)
__device__ __nv_bfloat16 g_x2[(long long)Mproj * 2048];  // [8192,2048] act hi|lo
__device__ __nv_bfloat16 g_w2[(long long)1024 * 2048];   // [1024,2048] wgt hi|lo
}

// ============================================================================
// Base-target PTX helpers (NO sm_103a-only instructions!)
// ============================================================================
__device__ __forceinline__ uint32_t smem_u32(const void* p) {
    uint32_t a;
    asm("{ .reg .u64 t; cvta.to.shared.u64 t, %1; cvt.u32.u64 %0, t; }"
        : "=r"(a) : "l"(p));
    return a;
}

__device__ __forceinline__ uint32_t sw128(uint32_t off) {
    return off ^ ((off >> 3) & 0x70);
}

#define LDMX4(r, addr)                                                        \
    asm volatile("ldmatrix.sync.aligned.m8n8.x4.shared.b16 {%0,%1,%2,%3}, [%4];" \
        : "=r"((r)[0]), "=r"((r)[1]), "=r"((r)[2]), "=r"((r)[3]) : "r"(addr))

__device__ __forceinline__ void mma_16816(float* d, const uint32_t* a,
                                          uint32_t b0, uint32_t b1) {
    asm volatile(
        "mma.sync.aligned.m16n8k16.row.col.f32.bf16.bf16.f32 "
        "{%0,%1,%2,%3}, {%4,%5,%6,%7}, {%8,%9}, {%0,%1,%2,%3};"
        : "+f"(d[0]), "+f"(d[1]), "+f"(d[2]), "+f"(d[3])
        : "r"(a[0]), "r"(a[1]), "r"(a[2]), "r"(a[3]), "r"(b0), "r"(b1));
}

#define CP_ASYNC16(dst, src) \
    asm volatile("cp.async.cg.shared.global [%0], [%1], 16;" :: "r"(dst), "l"(src))
#define CP_COMMIT()     asm volatile("cp.async.commit_group;" ::: "memory")
#define CP_WAIT(n)      asm volatile("cp.async.wait_group %0;" :: "n"(n) : "memory")

// ============================================================================
// HMMA bf16 GEMM:  C[8192,1024] = A2[8192,2048] x W2[1024,2048]^T  (NT)
// hi/lo split over 3 passes (Ah*Bh + Al*Bh + Ah*Bl), fp32 accum in registers.
// Block tile 128x128, 8 warps (2x4), warp tile 64x32, K-chunk 64 bf16.
// cp.async double-buffered. OMODE 0: planar head-split; 1: interleaved fp32.
// ============================================================================
namespace {
constexpr int NC = 48;   // 3 passes x 16 chunks of 64 over K=1024
constexpr int SM_BUF = 32768;           // A(16K) + B(16K) per buffer
constexpr int SM_TOTAL = 2 * SM_BUF + 1024;  // +1K for base alignment
}

template<int OMODE>
__global__ void __launch_bounds__(256, 1)
tgemm_kernel(const uint4* __restrict__ A2,   // [M, 2048] bf16 = 256 uint4/row
             const uint4* __restrict__ B2,   // [1024, 2048] bf16
             float* __restrict__ d0, float* __restrict__ d1)
{
    extern __shared__ char smem[];
    const uint32_t sbase = (smem_u32(smem) + 1023) & ~1023u;
    const int tid = threadIdx.x;
    const int lane = tid & 31, wid = tid >> 5;
    const int wm = wid & 1, wn = wid >> 1;       // warp grid 2 x 4
    const int m0 = blockIdx.y * 128, n0 = blockIdx.x * 128;

    float acc[4][4][4];
#pragma unroll
    for (int i = 0; i < 4; i++)
#pragma unroll
        for (int j = 0; j < 4; j++)
#pragma unroll
            for (int k = 0; k < 4; k++) acc[i][j][k] = 0.f;

    auto issue_chunk = [&](int c, int buf) {
        const int pass = c >> 4;
        const int kc = (c & 15) << 6;                       // bf16 col in [0,1024)
        const int ca = (kc + ((pass == 1) ? 1024 : 0)) >> 3;  // uint4 col
        const int cb = (kc + ((pass == 2) ? 1024 : 0)) >> 3;
        const uint32_t ab = sbase + buf * SM_BUF;
        const uint32_t bb = ab + 16384;
#pragma unroll
        for (int i = 0; i < 4; i++) {
            const int lin = tid + 256 * i;                  // 0..1023
            const int row = lin >> 3, seg = lin & 7;
            const uint32_t off = sw128((uint32_t)(row * 128 + seg * 16));
            CP_ASYNC16(ab + off, &A2[(size_t)(m0 + row) * 256 + ca + seg]);
            CP_ASYNC16(bb + off, &B2[(size_t)(n0 + row) * 256 + cb + seg]);
        }
        CP_COMMIT();
    };

    issue_chunk(0, 0);
    for (int c = 0; c < NC; c++) {
        const int buf = c & 1;
        if (c + 1 < NC) { issue_chunk(c + 1, buf ^ 1); CP_WAIT(1); }
        else            { CP_WAIT(0); }
        __syncthreads();

        const uint32_t ab = sbase + buf * SM_BUF;
        const uint32_t bb = ab + 16384;
#pragma unroll
        for (int kk = 0; kk < 4; kk++) {      // 4 x k16 per chunk
            uint32_t af[4][4];
#pragma unroll
            for (int mt = 0; mt < 4; mt++) {
                const int row = wm * 64 + mt * 16 + (lane & 15);
                LDMX4(af[mt], ab + sw128((uint32_t)(row * 128 + kk * 32 + (lane >> 4) * 16)));
            }
            uint32_t bf[2][4];
#pragma unroll
            for (int p = 0; p < 2; p++) {
                const int row = wn * 32 + p * 16 + (lane & 15);
                LDMX4(bf[p], bb + sw128((uint32_t)(row * 128 + kk * 32 + (lane >> 4) * 16)));
            }
#pragma unroll
            for (int mt = 0; mt < 4; mt++)
#pragma unroll
                for (int nt = 0; nt < 4; nt++)
                    mma_16816(acc[mt][nt], af[mt],
                              bf[nt >> 1][nt & 1], bf[nt >> 1][(nt & 1) + 2]);
        }
        __syncthreads();
    }

    // ------ epilogue: registers -> global ------
    const int qrow = lane >> 2, qcol = (lane & 3) * 2;
#pragma unroll
    for (int mt = 0; mt < 4; mt++)
#pragma unroll
        for (int nt = 0; nt < 4; nt++)
#pragma unroll
            for (int h2 = 0; h2 < 2; h2++) {
                const int m = m0 + wm * 64 + mt * 16 + qrow + 8 * h2;
                const int n = n0 + wn * 32 + nt * 8 + qcol;
                const float v0 = acc[mt][nt][2 * h2];
                const float v1 = acc[mt][nt][2 * h2 + 1];
                const int comp = n >> 9, f = n & 511;
                if (OMODE == 0) {
                    const int hh = f >> 6, dh = f & 63;
                    float* dst = (comp ? d1 : d0)
                        + (((long long)((m >> 10) * Hn + hh) * Sn + (m & 1023)) * DHn + dh);
                    dst[0] = v0; dst[1] = v1;
                } else {
                    float* dst = d0 + ((long long)m * 1024 + (long long)f * 2 + comp);
                    dst[0] = v0; dst[2] = v1;
                }
            }
}

// ============================================================================
// Conversion kernels: fp32 -> bf16 hi/lo split layouts
// ============================================================================
__device__ __forceinline__ uint4 pack8(const __nv_bfloat16* v) {
    union { __nv_bfloat16 b[8]; uint4 u; } P;
#pragma unroll
    for (int i = 0; i < 8; i++) P.b[i] = v[i];
    return P.u;
}

// in: [M, 512] complex fp32. out: [M, 2048] bf16
// cols [0,512)=hi(re), [512,1024)=hi(im), [1024,1536)=lo(re), [1536,2048)=lo(im)
__global__ void __launch_bounds__(256)
convx_kernel(const float2* __restrict__ in, __nv_bfloat16* __restrict__ out)
{
    const int idx = blockIdx.x * 256 + threadIdx.x;   // 1048576 total
    const int m = idx >> 7;
    const int comp = (idx >> 6) & 1;
    const int f8 = (idx & 63) * 8;
    const float2* src = in + (long long)m * 512 + f8;
    __nv_bfloat16 hi[8], lo[8];
#pragma unroll
    for (int j = 0; j < 8; j++) {
        const float x = comp ? src[j].y : src[j].x;
        const __nv_bfloat16 h = __float2bfloat16_rn(x);
        hi[j] = h;
        lo[j] = __float2bfloat16_rn(x - __bfloat162float(h));
    }
    __nv_bfloat16* dst = out + (long long)m * 2048 + comp * 512 + f8;
    *(uint4*)dst = pack8(hi);
    *(uint4*)(dst + 1024) = pack8(lo);
}

// weights wr, wi [512,512] -> W2 [1024, 2048]
// row n<512 (y_r):  [hi(wr[n]) | hi(-wi[n]) | lo(wr[n]) | lo(-wi[n])]
// row n>=512 (y_i): [hi(wi[n']) | hi(wr[n']) | lo(wi[n']) | lo(wr[n'])]
__global__ void __launch_bounds__(256)
convw_kernel(const float* __restrict__ wr, const float* __restrict__ wi,
             __nv_bfloat16* __restrict__ out)
{
    const int idx = blockIdx.x * 256 + threadIdx.x;   // 131072 total
    const int n = idx >> 7;
    const int half = (idx >> 6) & 1;
    const int f8 = (idx & 63) * 8;
    const float* src;
    float sgn = 1.f;
    if (n < 512) { src = (half ? wi : wr) + (long long)n * 512; if (half) sgn = -1.f; }
    else         { src = (half ? wr : wi) + (long long)(n - 512) * 512; }
    __nv_bfloat16 hi[8], lo[8];
#pragma unroll
    for (int j = 0; j < 8; j++) {
        const float x = sgn * src[f8 + j];
        const __nv_bfloat16 h = __float2bfloat16_rn(x);
        hi[j] = h;
        lo[j] = __float2bfloat16_rn(x - __bfloat162float(h));
    }
    __nv_bfloat16* dst = out + (long long)n * 2048 + half * 512 + f8;
    *(uint4*)dst = pack8(hi);
    *(uint4*)(dst + 1024) = pack8(lo);
}

// ============================================================================
// SIMT score GEMM (planar Q,K):  s = scale * q . k   (complex, NT)
// ============================================================================
__global__ void __launch_bounds__(256)
score_kernel(const float* __restrict__ qr, const float* __restrict__ qi,
             const float* __restrict__ kr, const float* __restrict__ ki,
             float2* __restrict__ C, float alpha)
{
    __shared__ float2 As[16][65];
    __shared__ float2 Bs[16][65];
    const int tid = threadIdx.x;
    const int tx = tid & 15, ty = tid >> 4;
    const int z = blockIdx.z;
    const int m0 = blockIdx.y * 64, n0 = blockIdx.x * 64;
    const long long zoff = (long long)z * Sn * DHn;

    float2 acc[4][4];
#pragma unroll
    for (int i = 0; i < 4; i++)
#pragma unroll
        for (int j = 0; j < 4; j++) acc[i][j] = make_float2(0.f, 0.f);

    const int r = tid >> 4, c = tid & 15;
    for (int k0 = 0; k0 < DHn; k0 += 16) {
#pragma unroll
        for (int q = 0; q < 4; q++) {
            const long long ia = zoff + (long long)(m0 + r + 16 * q) * DHn + k0 + c;
            As[c][r + 16 * q] = make_float2(qr[ia], qi[ia]);
            const long long ib = zoff + (long long)(n0 + r + 16 * q) * DHn + k0 + c;
            Bs[c][r + 16 * q] = make_float2(kr[ib], ki[ib]);
        }
        __syncthreads();
#pragma unroll
        for (int kk = 0; kk < 16; kk++) {
            float2 a[4], b[4];
#pragma unroll
            for (int i = 0; i < 4; i++) a[i] = As[kk][ty + 16 * i];
#pragma unroll
            for (int j = 0; j < 4; j++) b[j] = Bs[kk][tx + 16 * j];
#pragma unroll
            for (int i = 0; i < 4; i++)
#pragma unroll
                for (int j = 0; j < 4; j++) {
                    acc[i][j].x = fmaf(a[i].x, b[j].x, acc[i][j].x);
                    acc[i][j].x = fmaf(-a[i].y, b[j].y, acc[i][j].x);
                    acc[i][j].y = fmaf(a[i].x, b[j].y, acc[i][j].y);
                    acc[i][j].y = fmaf(a[i].y, b[j].x, acc[i][j].y);
                }
        }
        __syncthreads();
    }
#pragma unroll
    for (int i = 0; i < 4; i++)
#pragma unroll
        for (int j = 0; j < 4; j++) {
            const int m = m0 + ty + 16 * i, n = n0 + tx + 16 * j;
            C[(long long)z * Sn * Sn + (long long)m * Sn + n] =
                make_float2(acc[i][j].x * alpha, acc[i][j].y * alpha);
        }
}

// ============================================================================
// SIMT PV GEMM: o = probs(complex, interleaved) @ V(planar, NN)
// ============================================================================
__global__ void __launch_bounds__(256)
pv_kernel(const float2* __restrict__ A, const float* __restrict__ vr,
          const float* __restrict__ vi, float2* __restrict__ C)
{
    __shared__ float2 As[16][65];
    __shared__ float2 Bs[16][65];
    const int tid = threadIdx.x;
    const int tx = tid & 15, ty = tid >> 4;
    const int z = blockIdx.z;
    const int m0 = blockIdx.y * 64;
    const long long zs = (long long)z * Sn * Sn;
    const long long zv = (long long)z * Sn * DHn;

    float2 acc[4][4];
#pragma unroll
    for (int i = 0; i < 4; i++)
#pragma unroll
        for (int j = 0; j < 4; j++) acc[i][j] = make_float2(0.f, 0.f);

    const int r = tid >> 4, c = tid & 15;
    const int kkb = tid >> 6, nn = tid & 63;
    for (int k0 = 0; k0 < Sn; k0 += 16) {
#pragma unroll
        for (int q = 0; q < 4; q++)
            As[c][r + 16 * q] = A[zs + (long long)(m0 + r + 16 * q) * Sn + k0 + c];
#pragma unroll
        for (int q = 0; q < 4; q++) {
            const long long ib = zv + (long long)(k0 + kkb + 4 * q) * DHn + nn;
            Bs[kkb + 4 * q][nn] = make_float2(vr[ib], vi[ib]);
        }
        __syncthreads();
#pragma unroll
        for (int kk = 0; kk < 16; kk++) {
            float2 a[4], b[4];
#pragma unroll
            for (int i = 0; i < 4; i++) a[i] = As[kk][ty + 16 * i];
#pragma unroll
            for (int j = 0; j < 4; j++) b[j] = Bs[kk][tx + 16 * j];
#pragma unroll
            for (int i = 0; i < 4; i++)
#pragma unroll
                for (int j = 0; j < 4; j++) {
                    acc[i][j].x = fmaf(a[i].x, b[j].x, acc[i][j].x);
                    acc[i][j].x = fmaf(-a[i].y, b[j].y, acc[i][j].x);
                    acc[i][j].y = fmaf(a[i].x, b[j].y, acc[i][j].y);
                    acc[i][j].y = fmaf(a[i].y, b[j].x, acc[i][j].y);
                }
        }
        __syncthreads();
    }
#pragma unroll
    for (int i = 0; i < 4; i++)
#pragma unroll
        for (int j = 0; j < 4; j++) {
            const int m = m0 + ty + 16 * i, n = tx + 16 * j;
            const long long idx = (long long)(z >> 3) * ((long long)Sn * Dn)
                                  + (long long)(z & 7) * DHn
                                  + (long long)m * Dn + n;
            C[idx] = acc[i][j];
        }
}

// ============================================================================
// Row softmax (in place), real & imag components independently.
// ============================================================================
__global__ void __launch_bounds__(256)
softmax_kernel(float2* __restrict__ s)
{
    float2* p = s + (long long)blockIdx.x * Sn;
    const int tid = threadIdx.x;
    float2 v[4];
    float mx = -1e30f, my = -1e30f;
#pragma unroll
    for (int q = 0; q < 4; q++) {
        v[q] = p[tid + 256 * q];
        mx = fmaxf(mx, v[q].x);
        my = fmaxf(my, v[q].y);
    }
    __shared__ float red0[8], red1[8];
#pragma unroll
    for (int o = 16; o > 0; o >>= 1) {
        mx = fmaxf(mx, __shfl_xor_sync(0xffffffffu, mx, o));
        my = fmaxf(my, __shfl_xor_sync(0xffffffffu, my, o));
    }
    const int wid = tid >> 5, lane = tid & 31;
    if (lane == 0) { red0[wid] = mx; red1[wid] = my; }
    __syncthreads();
    mx = red0[0]; my = red1[0];
#pragma unroll
    for (int w = 1; w < 8; w++) { mx = fmaxf(mx, red0[w]); my = fmaxf(my, red1[w]); }
    float sx = 0.f, sy = 0.f;
#pragma unroll
    for (int q = 0; q < 4; q++) {
        v[q].x = __expf(v[q].x - mx);
        v[q].y = __expf(v[q].y - my);
        sx += v[q].x; sy += v[q].y;
    }
#pragma unroll
    for (int o = 16; o > 0; o >>= 1) {
        sx += __shfl_xor_sync(0xffffffffu, sx, o);
        sy += __shfl_xor_sync(0xffffffffu, sy, o);
    }
    __syncthreads();
    if (lane == 0) { red0[wid] = sx; red1[wid] = sy; }
    __syncthreads();
    sx = 0.f; sy = 0.f;
#pragma unroll
    for (int w = 0; w < 8; w++) { sx += red0[w]; sy += red1[w]; }
    const float rx = 1.f / sx, ry = 1.f / sy;
#pragma unroll
    for (int q = 0; q < 4; q++)
        p[tid + 256 * q] = make_float2(v[q].x * rx, v[q].y * ry);
}

// ============================================================================
extern "C" void kernel_launch(void* const* d_in, const int* in_sizes, int n_in,
                              void* d_out, int out_size)
{
    (void)in_sizes; (void)n_in; (void)out_size;
    const float2* Qin = (const float2*)d_in[0];
    const float2* Kin = (const float2*)d_in[1];
    const float2* Vin = (const float2*)d_in[2];
    const float* wq_r = (const float*)d_in[3];
    const float* wq_i = (const float*)d_in[4];
    const float* wk_r = (const float*)d_in[5];
    const float* wk_i = (const float*)d_in[6];
    const float* wv_r = (const float*)d_in[7];
    const float* wv_i = (const float*)d_in[8];
    const float* wo_r = (const float*)d_in[9];
    const float* wo_i = (const float*)d_in[10];

    float *qr, *qi, *kr, *ki, *vr, *vi;
    float2 *o, *s;
    __nv_bfloat16 *x2, *w2;
    cudaGetSymbolAddress((void**)&qr, g_qr);
    cudaGetSymbolAddress((void**)&qi, g_qi);
    cudaGetSymbolAddress((void**)&kr, g_kr);
    cudaGetSymbolAddress((void**)&ki, g_ki);
    cudaGetSymbolAddress((void**)&vr, g_vr);
    cudaGetSymbolAddress((void**)&vi, g_vi);
    cudaGetSymbolAddress((void**)&o, g_o);
    cudaGetSymbolAddress((void**)&s, g_s);
    cudaGetSymbolAddress((void**)&x2, g_x2);
    cudaGetSymbolAddress((void**)&w2, g_w2);

    cudaFuncSetAttribute(tgemm_kernel<0>, cudaFuncAttributeMaxDynamicSharedMemorySize, SM_TOTAL);
    cudaFuncSetAttribute(tgemm_kernel<1>, cudaFuncAttributeMaxDynamicSharedMemorySize, SM_TOTAL);

    const dim3 gt(1024 / 128, Mproj / 128);   // (8, 64)
    const uint4* x4 = (const uint4*)x2;
    const uint4* w4 = (const uint4*)w2;

    // --- Q projection ---
    convx_kernel<<<4096, 256>>>(Qin, x2);
    convw_kernel<<<512, 256>>>(wq_r, wq_i, w2);
    tgemm_kernel<0><<<gt, 256, SM_TOTAL>>>(x4, w4, qr, qi);
    // --- K projection ---
    convx_kernel<<<4096, 256>>>(Kin, x2);
    convw_kernel<<<512, 256>>>(wk_r, wk_i, w2);
    tgemm_kernel<0><<<gt, 256, SM_TOTAL>>>(x4, w4, kr, ki);
    // --- V projection ---
    convx_kernel<<<4096, 256>>>(Vin, x2);
    convw_kernel<<<512, 256>>>(wv_r, wv_i, w2);
    tgemm_kernel<0><<<gt, 256, SM_TOTAL>>>(x4, w4, vr, vi);

    // --- scores ---
    const dim3 gsc(Sn / 64, Sn / 64, Bn * Hn);
    score_kernel<<<gsc, 256>>>(qr, qi, kr, ki, s, 0.125f);

    // --- softmax ---
    softmax_kernel<<<Bn * Hn * Sn, 256>>>(s);

    // --- PV ---
    const dim3 gpv(1, Sn / 64, Bn * Hn);
    pv_kernel<<<gpv, 256>>>(s, vr, vi, o);

    // --- output projection ---
    convx_kernel<<<4096, 256>>>(o, x2);
    convw_kernel<<<512, 256>>>(wo_r, wo_i, w2);
    tgemm_kernel<1><<<gt, 256, SM_TOTAL>>>(x4, w4, (float*)d_out, nullptr);
}

// round 5
// speedup vs baseline: 1.6309x; 1.2386x over previous
#include <cuda_runtime.h>
#include <cuda_bf16.h>
#include <cstdint>

// ============================================================================
// Problem constants
// ============================================================================
namespace {
constexpr int Bn = 8;
constexpr int Sn = 1024;
constexpr int Dn = 512;
constexpr int Hn = 8;
constexpr int DHn = 64;
constexpr int Mproj = Bn * Sn;                                   // 8192
constexpr long long S_ELEMS = (long long)Bn * Hn * Sn * Sn;      // 64M complex

// Scratch (device globals; allocation-free per harness rules)
__device__ float g_vr[(long long)Bn * Hn * Sn * DHn];   // planar V fp32
__device__ float g_vi[(long long)Bn * Hn * Sn * DHn];
__device__ float2 g_o[(long long)Bn * Sn * Dn];         // attn out [B,S,D]
__device__ float2 g_s[S_ELEMS];                         // scores fp32 (512MB)
__device__ __nv_bfloat16 g_x2[(long long)Mproj * 2048]; // act hi|lo for proj
__device__ __nv_bfloat16 g_w2[(long long)1024 * 2048];  // wgt hi|lo for proj
__device__ __nv_bfloat16 g_qb[(long long)64 * 1024 * 256];   // Q score-operand
__device__ __nv_bfloat16 g_kb[(long long)64 * 2048 * 256];   // K score-operand
__device__ __nv_bfloat16 g_vb[(long long)64 * 128 * 4096];   // V pv-operand
__device__ __nv_bfloat16 g_pb[(long long)64 * 1024 * 4096];  // probs pv-operand
}

// ============================================================================
// Base-target PTX helpers (no sm_103a-only instructions)
// ============================================================================
__device__ __forceinline__ uint32_t smem_u32(const void* p) {
    uint32_t a;
    asm("{ .reg .u64 t; cvta.to.shared.u64 t, %1; cvt.u32.u64 %0, t; }"
        : "=r"(a) : "l"(p));
    return a;
}
__device__ __forceinline__ uint32_t sw128(uint32_t off) {
    return off ^ ((off >> 3) & 0x70);
}
#define LDMX4(r, addr)                                                        \
    asm volatile("ldmatrix.sync.aligned.m8n8.x4.shared.b16 {%0,%1,%2,%3}, [%4];" \
        : "=r"((r)[0]), "=r"((r)[1]), "=r"((r)[2]), "=r"((r)[3]) : "r"(addr))
__device__ __forceinline__ void mma_16816(float* d, const uint32_t* a,
                                          uint32_t b0, uint32_t b1) {
    asm volatile(
        "mma.sync.aligned.m16n8k16.row.col.f32.bf16.bf16.f32 "
        "{%0,%1,%2,%3}, {%4,%5,%6,%7}, {%8,%9}, {%0,%1,%2,%3};"
        : "+f"(d[0]), "+f"(d[1]), "+f"(d[2]), "+f"(d[3])
        : "r"(a[0]), "r"(a[1]), "r"(a[2]), "r"(a[3]), "r"(b0), "r"(b1));
}
#define CP_ASYNC16(dst, src) \
    asm volatile("cp.async.cg.shared.global [%0], [%1], 16;" :: "r"(dst), "l"(src))
#define CP_COMMIT()     asm volatile("cp.async.commit_group;" ::: "memory")
#define CP_WAIT(n)      asm volatile("cp.async.wait_group %0;" :: "n"(n) : "memory")

namespace {
constexpr int SM_BUF = 32768;                 // A(16K)+B(16K) per buffer
constexpr int SM_TOTAL = 2 * SM_BUF + 1024;
}

__device__ __forceinline__ uint4 pack8(const __nv_bfloat16* v) {
    union { __nv_bfloat16 b[8]; uint4 u; } P;
#pragma unroll
    for (int i = 0; i < 8; i++) P.b[i] = v[i];
    return P.u;
}

// ============================================================================
// Projection GEMM: C[8192,1024] = X2[8192,2048] x W2[1024,2048]^T (NT, bf16
// hi/lo 3-pass, fp32 accum). OMODE epilogues:
//   0: Q -> g_qb [z=(b,h)][s][qr_hi|qi_hi(128) | qr_lo|qi_lo(128)]
//   1: K -> g_kb [z][2t:real form, 2t+1:imag form][256]
//   2: V -> planar fp32 g_vr/g_vi [z][s][dh]
//   3: out -> d_out interleaved [B,S,D,2] fp32
// ============================================================================
template<int OMODE>
__device__ __forceinline__ void store_proj(float v, int m, int n,
    __nv_bfloat16* qb, __nv_bfloat16* kb, float* f0, float* f1)
{
    const int comp = n >> 9, f = n & 511, hh = f >> 6, dh = f & 63;
    if (OMODE == 3) {
        f0[(size_t)m * 1024 + (size_t)f * 2 + comp] = v;
        return;
    }
    const int z = ((m >> 10) << 3) + hh;
    const int s = m & 1023;
    if (OMODE == 2) {
        (comp ? f1 : f0)[((size_t)z * 1024 + s) * 64 + dh] = v;
        return;
    }
    const __nv_bfloat16 h = __float2bfloat16_rn(v);
    const __nv_bfloat16 l = __float2bfloat16_rn(v - __bfloat162float(h));
    if (OMODE == 0) {
        const size_t base = ((size_t)z * 1024 + s) * 256 + comp * 64 + dh;
        qb[base] = h; qb[base + 128] = l;
    } else {  // OMODE == 1 (K)
        const size_t r0 = ((size_t)z * 2048 + 2 * s) * 256;
        const size_t r1 = r0 + 256;
        if (comp == 0) {        // kr: real row cols [0,64), imag row cols [64,128)
            kb[r0 + dh] = h;       kb[r0 + 128 + dh] = l;
            kb[r1 + 64 + dh] = h;  kb[r1 + 192 + dh] = l;
        } else {                // ki: real row gets -ki, imag row gets +ki
            kb[r0 + 64 + dh] = __hneg(h); kb[r0 + 192 + dh] = __hneg(l);
            kb[r1 + dh] = h;       kb[r1 + 128 + dh] = l;
        }
    }
}

template<int OMODE>
__global__ void __launch_bounds__(256, 1)
tgemm_kernel(const uint4* __restrict__ A2, const uint4* __restrict__ B2,
             float* __restrict__ f0, float* __restrict__ f1,
             __nv_bfloat16* __restrict__ qb, __nv_bfloat16* __restrict__ kb)
{
    extern __shared__ char smem[];
    const uint32_t sbase = (smem_u32(smem) + 1023) & ~1023u;
    const int tid = threadIdx.x;
    const int lane = tid & 31, wid = tid >> 5;
    const int wm = wid & 1, wn = wid >> 1;
    const int m0 = blockIdx.y * 128, n0 = blockIdx.x * 128;

    float acc[4][4][4];
#pragma unroll
    for (int i = 0; i < 4; i++)
#pragma unroll
        for (int j = 0; j < 4; j++)
#pragma unroll
            for (int k = 0; k < 4; k++) acc[i][j][k] = 0.f;

    auto issue_chunk = [&](int c, int buf) {
        const int pass = c >> 4;
        const int kc = (c & 15) << 6;
        const int ca = (kc + ((pass == 1) ? 1024 : 0)) >> 3;
        const int cb = (kc + ((pass == 2) ? 1024 : 0)) >> 3;
        const uint32_t ab = sbase + buf * SM_BUF;
        const uint32_t bb = ab + 16384;
#pragma unroll
        for (int i = 0; i < 4; i++) {
            const int lin = tid + 256 * i;
            const int row = lin >> 3, seg = lin & 7;
            const uint32_t off = sw128((uint32_t)(row * 128 + seg * 16));
            CP_ASYNC16(ab + off, &A2[(size_t)(m0 + row) * 256 + ca + seg]);
            CP_ASYNC16(bb + off, &B2[(size_t)(n0 + row) * 256 + cb + seg]);
        }
        CP_COMMIT();
    };

    constexpr int NC = 48;
    issue_chunk(0, 0);
    for (int c = 0; c < NC; c++) {
        const int buf = c & 1;
        if (c + 1 < NC) { issue_chunk(c + 1, buf ^ 1); CP_WAIT(1); }
        else            { CP_WAIT(0); }
        __syncthreads();
        const uint32_t ab = sbase + buf * SM_BUF;
        const uint32_t bb = ab + 16384;
#pragma unroll
        for (int kk = 0; kk < 4; kk++) {
            uint32_t af[4][4];
#pragma unroll
            for (int mt = 0; mt < 4; mt++) {
                const int row = wm * 64 + mt * 16 + (lane & 15);
                LDMX4(af[mt], ab + sw128((uint32_t)(row * 128 + kk * 32 + (lane >> 4) * 16)));
            }
            uint32_t bf[2][4];
#pragma unroll
            for (int p = 0; p < 2; p++) {
                const int row = wn * 32 + p * 16 + (lane & 15);
                LDMX4(bf[p], bb + sw128((uint32_t)(row * 128 + kk * 32 + (lane >> 4) * 16)));
            }
#pragma unroll
            for (int mt = 0; mt < 4; mt++)
#pragma unroll
                for (int nt = 0; nt < 4; nt++)
                    mma_16816(acc[mt][nt], af[mt],
                              bf[nt >> 1][nt & 1], bf[nt >> 1][(nt & 1) + 2]);
        }
        __syncthreads();
    }

    const int qrow = lane >> 2, qcol = (lane & 3) * 2;
#pragma unroll
    for (int mt = 0; mt < 4; mt++)
#pragma unroll
        for (int nt = 0; nt < 4; nt++)
#pragma unroll
            for (int h2 = 0; h2 < 2; h2++) {
                const int m = m0 + wm * 64 + mt * 16 + qrow + 8 * h2;
                const int n = n0 + wn * 32 + nt * 8 + qcol;
                store_proj<OMODE>(acc[mt][nt][2 * h2],     m, n,     qb, kb, f0, f1);
                store_proj<OMODE>(acc[mt][nt][2 * h2 + 1], m, n + 1, qb, kb, f0, f1);
            }
}

// ============================================================================
// Attention GEMM (HMMA, generalized addressing, hi/lo 3 passes):
//   OMODE 2 (scores): A=g_qb[z,1024,256], B=g_kb[z,2048,256]
//       -> fp32 interleaved complex scores, scaled.
//   OMODE 3 (PV): A=g_pb[z,1024,4096], B=g_vb[z,128,4096] -> attn out fp32.
// ============================================================================
template<int OMODE>
__global__ void __launch_bounds__(256, 1)
hgemm_kernel(const uint4* __restrict__ A, int aRow, long long aZ,
             int ao0, int ao1, int ao2,
             const uint4* __restrict__ B, int bRow, long long bZ,
             int bo0, int bo1, int bo2,
             int npc, float* __restrict__ out, float scale)
{
    extern __shared__ char smem[];
    const uint32_t sbase = (smem_u32(smem) + 1023) & ~1023u;
    const int tid = threadIdx.x;
    const int lane = tid & 31, wid = tid >> 5;
    const int wm = wid & 1, wn = wid >> 1;
    const int z = blockIdx.z;
    const int m0 = blockIdx.y * 128, n0 = blockIdx.x * 128;
    const uint4* Az = A + (long long)z * aZ;
    const uint4* Bz = B + (long long)z * bZ;
    const int NC = 3 * npc;

    float acc[4][4][4];
#pragma unroll
    for (int i = 0; i < 4; i++)
#pragma unroll
        for (int j = 0; j < 4; j++)
#pragma unroll
            for (int k = 0; k < 4; k++) acc[i][j][k] = 0.f;

    auto issue_chunk = [&](int c, int buf) {
        const int pass = (c >= 2 * npc) ? 2 : ((c >= npc) ? 1 : 0);
        const int kc = (c - pass * npc) * 8;
        const int ca = ((pass == 0) ? ao0 : (pass == 1) ? ao1 : ao2) + kc;
        const int cb = ((pass == 0) ? bo0 : (pass == 1) ? bo1 : bo2) + kc;
        const uint32_t ab = sbase + buf * SM_BUF;
        const uint32_t bb = ab + 16384;
#pragma unroll
        for (int i = 0; i < 4; i++) {
            const int lin = tid + 256 * i;
            const int row = lin >> 3, seg = lin & 7;
            const uint32_t off = sw128((uint32_t)(row * 128 + seg * 16));
            CP_ASYNC16(ab + off, &Az[(size_t)(m0 + row) * aRow + ca + seg]);
            CP_ASYNC16(bb + off, &Bz[(size_t)(n0 + row) * bRow + cb + seg]);
        }
        CP_COMMIT();
    };

    issue_chunk(0, 0);
    for (int c = 0; c < NC; c++) {
        const int buf = c & 1;
        if (c + 1 < NC) { issue_chunk(c + 1, buf ^ 1); CP_WAIT(1); }
        else            { CP_WAIT(0); }
        __syncthreads();
        const uint32_t ab = sbase + buf * SM_BUF;
        const uint32_t bb = ab + 16384;
#pragma unroll
        for (int kk = 0; kk < 4; kk++) {
            uint32_t af[4][4];
#pragma unroll
            for (int mt = 0; mt < 4; mt++) {
                const int row = wm * 64 + mt * 16 + (lane & 15);
                LDMX4(af[mt], ab + sw128((uint32_t)(row * 128 + kk * 32 + (lane >> 4) * 16)));
            }
            uint32_t bf[2][4];
#pragma unroll
            for (int p = 0; p < 2; p++) {
                const int row = wn * 32 + p * 16 + (lane & 15);
                LDMX4(bf[p], bb + sw128((uint32_t)(row * 128 + kk * 32 + (lane >> 4) * 16)));
            }
#pragma unroll
            for (int mt = 0; mt < 4; mt++)
#pragma unroll
                for (int nt = 0; nt < 4; nt++)
                    mma_16816(acc[mt][nt], af[mt],
                              bf[nt >> 1][nt & 1], bf[nt >> 1][(nt & 1) + 2]);
        }
        __syncthreads();
    }

    const int qrow = lane >> 2, qcol = (lane & 3) * 2;
#pragma unroll
    for (int mt = 0; mt < 4; mt++)
#pragma unroll
        for (int nt = 0; nt < 4; nt++)
#pragma unroll
            for (int h2 = 0; h2 < 2; h2++) {
                const int m = m0 + wm * 64 + mt * 16 + qrow + 8 * h2;
                const int n = n0 + wn * 32 + nt * 8 + qcol;   // even
                const float v0 = acc[mt][nt][2 * h2] * scale;
                const float v1 = acc[mt][nt][2 * h2 + 1] * scale;
                float* dst;
                if (OMODE == 2) {
                    dst = out + (long long)z * (1024LL * 2048) + (long long)m * 2048 + n;
                } else {
                    const int dh = n >> 1;
                    dst = out + ((((long long)(z >> 3) * 1024 + m) * 512)
                                 + (z & 7) * 64 + dh) * 2;
                }
                dst[0] = v0; dst[1] = v1;
            }
}

// ============================================================================
// V operand transpose: planar fp32 [z][s][dh] -> g_vb B-form [z][n][k] bf16
//   row n=2dh:   k=2s -> vr,  k=2s+1 -> -vi    (hi at col, lo at col+2048)
//   row n=2dh+1: k=2s -> vi,  k=2s+1 -> vr
// ============================================================================
__global__ void __launch_bounds__(256)
vconv_kernel(const float* __restrict__ vr, const float* __restrict__ vi,
             __nv_bfloat16* __restrict__ vb)
{
    __shared__ float tile[2][64][65];
    const int z = blockIdx.y, s0 = blockIdx.x * 64;
    const int tid = threadIdx.x;
#pragma unroll
    for (int i = 0; i < 16; i++) {
        const int idx = tid + 256 * i;           // 4096
        const int row = idx >> 6, c = idx & 63;
        const size_t g = ((size_t)z * 1024 + s0 + row) * 64 + c;
        tile[0][row][c] = vr[g];
        tile[1][row][c] = vi[g];
    }
    __syncthreads();
    const int r = tid >> 1, h4 = tid & 1;        // r = output row n (0..127)
    const int dh = r >> 1, ci = r & 1;
    __nv_bfloat16 hb[64], lb[64];
#pragma unroll
    for (int j = 0; j < 64; j++) {
        const int s = (h4 * 64 + j) >> 1, ck = j & 1;
        float v;
        if (ci == 0) v = ck ? -tile[1][s][dh] : tile[0][s][dh];
        else         v = ck ?  tile[0][s][dh] : tile[1][s][dh];
        const __nv_bfloat16 h = __float2bfloat16_rn(v);
        hb[j] = h;
        lb[j] = __float2bfloat16_rn(v - __bfloat162float(h));
    }
    const size_t base = ((size_t)z * 128 + r) * 4096 + 2 * s0 + h4 * 64;
#pragma unroll
    for (int u = 0; u < 8; u++) {
        *(uint4*)(vb + base + 8 * u) = pack8(hb + 8 * u);
        *(uint4*)(vb + base + 2048 + 8 * u) = pack8(lb + 8 * u);
    }
}

// ============================================================================
// fp32 -> bf16 hi/lo conversions for projections
// ============================================================================
__global__ void __launch_bounds__(256)
convx_kernel(const float2* __restrict__ in, __nv_bfloat16* __restrict__ out)
{
    const int idx = blockIdx.x * 256 + threadIdx.x;
    const int m = idx >> 7;
    const int comp = (idx >> 6) & 1;
    const int f8 = (idx & 63) * 8;
    const float2* src = in + (long long)m * 512 + f8;
    __nv_bfloat16 hi[8], lo[8];
#pragma unroll
    for (int j = 0; j < 8; j++) {
        const float x = comp ? src[j].y : src[j].x;
        const __nv_bfloat16 h = __float2bfloat16_rn(x);
        hi[j] = h;
        lo[j] = __float2bfloat16_rn(x - __bfloat162float(h));
    }
    __nv_bfloat16* dst = out + (long long)m * 2048 + comp * 512 + f8;
    *(uint4*)dst = pack8(hi);
    *(uint4*)(dst + 1024) = pack8(lo);
}

__global__ void __launch_bounds__(256)
convw_kernel(const float* __restrict__ wr, const float* __restrict__ wi,
             __nv_bfloat16* __restrict__ out)
{
    const int idx = blockIdx.x * 256 + threadIdx.x;
    const int n = idx >> 7;
    const int half = (idx >> 6) & 1;
    const int f8 = (idx & 63) * 8;
    const float* src;
    float sgn = 1.f;
    if (n < 512) { src = (half ? wi : wr) + (long long)n * 512; if (half) sgn = -1.f; }
    else         { src = (half ? wr : wi) + (long long)(n - 512) * 512; }
    __nv_bfloat16 hi[8], lo[8];
#pragma unroll
    for (int j = 0; j < 8; j++) {
        const float x = sgn * src[f8 + j];
        const __nv_bfloat16 h = __float2bfloat16_rn(x);
        hi[j] = h;
        lo[j] = __float2bfloat16_rn(x - __bfloat162float(h));
    }
    __nv_bfloat16* dst = out + (long long)n * 2048 + half * 512 + f8;
    *(uint4*)dst = pack8(hi);
    *(uint4*)(dst + 1024) = pack8(lo);
}

// ============================================================================
// Row softmax over fp32 scores; emits probs as bf16 hi/lo interleaved (g_pb).
// ============================================================================
__global__ void __launch_bounds__(256)
softmax_kernel(const float2* __restrict__ s, __nv_bfloat16* __restrict__ pbuf)
{
    const float2* p = s + (long long)blockIdx.x * Sn;
    const int tid = threadIdx.x;
    float2 v[4];
    float mx = -1e30f, my = -1e30f;
#pragma unroll
    for (int q = 0; q < 4; q++) {
        v[q] = p[tid + 256 * q];
        mx = fmaxf(mx, v[q].x);
        my = fmaxf(my, v[q].y);
    }
    __shared__ float red0[8], red1[8];
#pragma unroll
    for (int o = 16; o > 0; o >>= 1) {
        mx = fmaxf(mx, __shfl_xor_sync(0xffffffffu, mx, o));
        my = fmaxf(my, __shfl_xor_sync(0xffffffffu, my, o));
    }
    const int wid = tid >> 5, lane = tid & 31;
    if (lane == 0) { red0[wid] = mx; red1[wid] = my; }
    __syncthreads();
    mx = red0[0]; my = red1[0];
#pragma unroll
    for (int w = 1; w < 8; w++) { mx = fmaxf(mx, red0[w]); my = fmaxf(my, red1[w]); }
    float sx = 0.f, sy = 0.f;
#pragma unroll
    for (int q = 0; q < 4; q++) {
        v[q].x = __expf(v[q].x - mx);
        v[q].y = __expf(v[q].y - my);
        sx += v[q].x; sy += v[q].y;
    }
#pragma unroll
    for (int o = 16; o > 0; o >>= 1) {
        sx += __shfl_xor_sync(0xffffffffu, sx, o);
        sy += __shfl_xor_sync(0xffffffffu, sy, o);
    }
    __syncthreads();
    if (lane == 0) { red0[wid] = sx; red1[wid] = sy; }
    __syncthreads();
    sx = 0.f; sy = 0.f;
#pragma unroll
    for (int w = 0; w < 8; w++) { sx += red0[w]; sy += red1[w]; }
    const float rx = 1.f / sx, ry = 1.f / sy;

    __nv_bfloat162* pb = (__nv_bfloat162*)(pbuf + (size_t)blockIdx.x * 4096);
#pragma unroll
    for (int q = 0; q < 4; q++) {
        const int t = tid + 256 * q;
        const float pr = v[q].x * rx, pi = v[q].y * ry;
        const __nv_bfloat16 hr = __float2bfloat16_rn(pr);
        const __nv_bfloat16 hi_ = __float2bfloat16_rn(pi);
        const __nv_bfloat16 lr = __float2bfloat16_rn(pr - __bfloat162float(hr));
        const __nv_bfloat16 li = __float2bfloat16_rn(pi - __bfloat162float(hi_));
        pb[t] = __halves2bfloat162(hr, hi_);
        pb[1024 + t] = __halves2bfloat162(lr, li);
    }
}

// ============================================================================
extern "C" void kernel_launch(void* const* d_in, const int* in_sizes, int n_in,
                              void* d_out, int out_size)
{
    (void)in_sizes; (void)n_in; (void)out_size;
    const float2* Qin = (const float2*)d_in[0];
    const float2* Kin = (const float2*)d_in[1];
    const float2* Vin = (const float2*)d_in[2];
    const float* wq_r = (const float*)d_in[3];
    const float* wq_i = (const float*)d_in[4];
    const float* wk_r = (const float*)d_in[5];
    const float* wk_i = (const float*)d_in[6];
    const float* wv_r = (const float*)d_in[7];
    const float* wv_i = (const float*)d_in[8];
    const float* wo_r = (const float*)d_in[9];
    const float* wo_i = (const float*)d_in[10];

    float *vr, *vi;
    float2 *o, *s;
    __nv_bfloat16 *x2, *w2, *qb, *kb, *vb, *pb;
    cudaGetSymbolAddress((void**)&vr, g_vr);
    cudaGetSymbolAddress((void**)&vi, g_vi);
    cudaGetSymbolAddress((void**)&o, g_o);
    cudaGetSymbolAddress((void**)&s, g_s);
    cudaGetSymbolAddress((void**)&x2, g_x2);
    cudaGetSymbolAddress((void**)&w2, g_w2);
    cudaGetSymbolAddress((void**)&qb, g_qb);
    cudaGetSymbolAddress((void**)&kb, g_kb);
    cudaGetSymbolAddress((void**)&vb, g_vb);
    cudaGetSymbolAddress((void**)&pb, g_pb);

    cudaFuncSetAttribute(tgemm_kernel<0>, cudaFuncAttributeMaxDynamicSharedMemorySize, SM_TOTAL);
    cudaFuncSetAttribute(tgemm_kernel<1>, cudaFuncAttributeMaxDynamicSharedMemorySize, SM_TOTAL);
    cudaFuncSetAttribute(tgemm_kernel<2>, cudaFuncAttributeMaxDynamicSharedMemorySize, SM_TOTAL);
    cudaFuncSetAttribute(tgemm_kernel<3>, cudaFuncAttributeMaxDynamicSharedMemorySize, SM_TOTAL);
    cudaFuncSetAttribute(hgemm_kernel<2>, cudaFuncAttributeMaxDynamicSharedMemorySize, SM_TOTAL);
    cudaFuncSetAttribute(hgemm_kernel<3>, cudaFuncAttributeMaxDynamicSharedMemorySize, SM_TOTAL);

    const dim3 gt(8, 64);                 // projection grid (1024/128, 8192/128)
    const uint4* x4 = (const uint4*)x2;
    const uint4* w4 = (const uint4*)w2;

    // --- Q projection -> score operand A ---
    convx_kernel<<<4096, 256>>>(Qin, x2);
    convw_kernel<<<512, 256>>>(wq_r, wq_i, w2);
    tgemm_kernel<0><<<gt, 256, SM_TOTAL>>>(x4, w4, nullptr, nullptr, qb, nullptr);
    // --- K projection -> score operand B ---
    convx_kernel<<<4096, 256>>>(Kin, x2);
    convw_kernel<<<512, 256>>>(wk_r, wk_i, w2);
    tgemm_kernel<1><<<gt, 256, SM_TOTAL>>>(x4, w4, nullptr, nullptr, nullptr, kb);
    // --- V projection -> planar fp32, then B-form transpose ---
    convx_kernel<<<4096, 256>>>(Vin, x2);
    convw_kernel<<<512, 256>>>(wv_r, wv_i, w2);
    tgemm_kernel<2><<<gt, 256, SM_TOTAL>>>(x4, w4, vr, vi, nullptr, nullptr);
    vconv_kernel<<<dim3(16, 64), 256>>>(vr, vi, vb);

    // --- scores: [1024 x 2048 x 3*128] per head, fp32 interleaved out ---
    hgemm_kernel<2><<<dim3(16, 8, 64), 256, SM_TOTAL>>>(
        (const uint4*)qb, 32, 32768LL, 0, 16, 0,
        (const uint4*)kb, 32, 65536LL, 0, 0, 16,
        2, (float*)s, 0.125f);

    // --- softmax -> probs bf16 hi/lo ---
    softmax_kernel<<<Bn * Hn * Sn, 256>>>(s, pb);

    // --- PV: [1024 x 128 x 3*2048] per head -> attn out fp32 ---
    hgemm_kernel<3><<<dim3(1, 8, 64), 256, SM_TOTAL>>>(
        (const uint4*)pb, 512, 524288LL, 0, 256, 0,
        (const uint4*)vb, 512, 65536LL, 0, 0, 256,
        32, (float*)o, 1.f);

    // --- output projection ---
    convx_kernel<<<4096, 256>>>(o, x2);
    convw_kernel<<<512, 256>>>(wo_r, wo_i, w2);
    tgemm_kernel<3><<<gt, 256, SM_TOTAL>>>(x4, w4, (float*)d_out, nullptr, nullptr, nullptr);
}

// round 6
// speedup vs baseline: 1.8256x; 1.1194x over previous
#include <cuda_runtime.h>
#include <cuda_bf16.h>
#include <cstdint>

// ============================================================================
// Problem constants
// ============================================================================
namespace {
constexpr int Bn = 8;
constexpr int Sn = 1024;
constexpr int Dn = 512;
constexpr int Hn = 8;
constexpr int Mproj = Bn * Sn;                                   // 8192

// Scratch (device globals; allocation-free per harness rules)
__device__ float g_vr[(long long)Bn * Hn * Sn * 64];    // planar V fp32
__device__ float g_vi[(long long)Bn * Hn * Sn * 64];
__device__ float2 g_o[(long long)Bn * Sn * Dn];         // attn out [B,S,D]
__device__ __nv_bfloat16 g_x2[(long long)Mproj * 2048]; // act hi|lo for proj
__device__ __nv_bfloat16 g_w2[(long long)1024 * 2048];  // wgt hi|lo for proj
__device__ __nv_bfloat16 g_qb[(long long)64 * 1024 * 256];  // Q score-operand
__device__ __nv_bfloat16 g_kb[(long long)64 * 2048 * 256];  // K score-operand
__device__ __nv_bfloat16 g_vb[(long long)64 * 128 * 2048];  // V natural operand
}

// ============================================================================
// Base-target PTX helpers
// ============================================================================
__device__ __forceinline__ uint32_t smem_u32(const void* p) {
    uint32_t a;
    asm("{ .reg .u64 t; cvta.to.shared.u64 t, %1; cvt.u32.u64 %0, t; }"
        : "=r"(a) : "l"(p));
    return a;
}
__device__ __forceinline__ uint32_t sw128(uint32_t off) {
    return off ^ ((off >> 3) & 0x70);
}
#define LDMX4(r, addr)                                                        \
    asm volatile("ldmatrix.sync.aligned.m8n8.x4.shared.b16 {%0,%1,%2,%3}, [%4];" \
        : "=r"((r)[0]), "=r"((r)[1]), "=r"((r)[2]), "=r"((r)[3]) : "r"(addr))
__device__ __forceinline__ void mma_16816(float* d, const uint32_t* a,
                                          uint32_t b0, uint32_t b1) {
    asm volatile(
        "mma.sync.aligned.m16n8k16.row.col.f32.bf16.bf16.f32 "
        "{%0,%1,%2,%3}, {%4,%5,%6,%7}, {%8,%9}, {%0,%1,%2,%3};"
        : "+f"(d[0]), "+f"(d[1]), "+f"(d[2]), "+f"(d[3])
        : "r"(a[0]), "r"(a[1]), "r"(a[2]), "r"(a[3]), "r"(b0), "r"(b1));
}
#define CP_ASYNC16(dst, src) \
    asm volatile("cp.async.cg.shared.global [%0], [%1], 16;" :: "r"(dst), "l"(src))
#define CP_COMMIT()     asm volatile("cp.async.commit_group;" ::: "memory")
#define CP_WAIT(n)      asm volatile("cp.async.wait_group %0;" :: "n"(n) : "memory")

__device__ __forceinline__ void sts_b16(uint32_t addr, __nv_bfloat16 v) {
    unsigned short u = *reinterpret_cast<unsigned short*>(&v);
    asm volatile("st.shared.b16 [%0], %1;" :: "r"(addr), "h"(u));
}

namespace {
constexpr int SM_BUF = 32768;
constexpr int SM_TOTAL = 2 * SM_BUF + 1024;
constexpr int SMF_TOTAL = 131072 + 4096 + 1024;  // Q+K+V+P tiles + red + align
}

__device__ __forceinline__ uint4 pack8(const __nv_bfloat16* v) {
    union { __nv_bfloat16 b[8]; uint4 u; } P;
#pragma unroll
    for (int i = 0; i < 8; i++) P.b[i] = v[i];
    return P.u;
}

// ============================================================================
// Projection GEMM (unchanged engine): C = X2 x W2^T, bf16 hi/lo 3-pass.
//   OMODE 0: Q -> g_qb; 1: K -> g_kb; 2: V -> planar fp32; 3: -> d_out
// ============================================================================
template<int OMODE>
__device__ __forceinline__ void store_proj(float v, int m, int n,
    __nv_bfloat16* qb, __nv_bfloat16* kb, float* f0, float* f1)
{
    const int comp = n >> 9, f = n & 511, hh = f >> 6, dh = f & 63;
    if (OMODE == 3) {
        f0[(size_t)m * 1024 + (size_t)f * 2 + comp] = v;
        return;
    }
    const int z = ((m >> 10) << 3) + hh;
    const int s = m & 1023;
    if (OMODE == 2) {
        (comp ? f1 : f0)[((size_t)z * 1024 + s) * 64 + dh] = v;
        return;
    }
    const __nv_bfloat16 h = __float2bfloat16_rn(v);
    const __nv_bfloat16 l = __float2bfloat16_rn(v - __bfloat162float(h));
    if (OMODE == 0) {
        const size_t base = ((size_t)z * 1024 + s) * 256 + comp * 64 + dh;
        qb[base] = h; qb[base + 128] = l;
    } else {
        const size_t r0 = ((size_t)z * 2048 + 2 * s) * 256;
        const size_t r1 = r0 + 256;
        if (comp == 0) {
            kb[r0 + dh] = h;       kb[r0 + 128 + dh] = l;
            kb[r1 + 64 + dh] = h;  kb[r1 + 192 + dh] = l;
        } else {
            kb[r0 + 64 + dh] = __hneg(h); kb[r0 + 192 + dh] = __hneg(l);
            kb[r1 + dh] = h;       kb[r1 + 128 + dh] = l;
        }
    }
}

template<int OMODE>
__global__ void __launch_bounds__(256, 1)
tgemm_kernel(const uint4* __restrict__ A2, const uint4* __restrict__ B2,
             float* __restrict__ f0, float* __restrict__ f1,
             __nv_bfloat16* __restrict__ qb, __nv_bfloat16* __restrict__ kb)
{
    extern __shared__ char smem[];
    const uint32_t sbase = (smem_u32(smem) + 1023) & ~1023u;
    const int tid = threadIdx.x;
    const int lane = tid & 31, wid = tid >> 5;
    const int wm = wid & 1, wn = wid >> 1;
    const int m0 = blockIdx.y * 128, n0 = blockIdx.x * 128;

    float acc[4][4][4];
#pragma unroll
    for (int i = 0; i < 4; i++)
#pragma unroll
        for (int j = 0; j < 4; j++)
#pragma unroll
            for (int k = 0; k < 4; k++) acc[i][j][k] = 0.f;

    auto issue_chunk = [&](int c, int buf) {
        const int pass = c >> 4;
        const int kc = (c & 15) << 6;
        const int ca = (kc + ((pass == 1) ? 1024 : 0)) >> 3;
        const int cb = (kc + ((pass == 2) ? 1024 : 0)) >> 3;
        const uint32_t ab = sbase + buf * SM_BUF;
        const uint32_t bb = ab + 16384;
#pragma unroll
        for (int i = 0; i < 4; i++) {
            const int lin = tid + 256 * i;
            const int row = lin >> 3, seg = lin & 7;
            const uint32_t off = sw128((uint32_t)(row * 128 + seg * 16));
            CP_ASYNC16(ab + off, &A2[(size_t)(m0 + row) * 256 + ca + seg]);
            CP_ASYNC16(bb + off, &B2[(size_t)(n0 + row) * 256 + cb + seg]);
        }
        CP_COMMIT();
    };

    constexpr int NC = 48;
    issue_chunk(0, 0);
    for (int c = 0; c < NC; c++) {
        const int buf = c & 1;
        if (c + 1 < NC) { issue_chunk(c + 1, buf ^ 1); CP_WAIT(1); }
        else            { CP_WAIT(0); }
        __syncthreads();
        const uint32_t ab = sbase + buf * SM_BUF;
        const uint32_t bb = ab + 16384;
#pragma unroll
        for (int kk = 0; kk < 4; kk++) {
            uint32_t af[4][4];
#pragma unroll
            for (int mt = 0; mt < 4; mt++) {
                const int row = wm * 64 + mt * 16 + (lane & 15);
                LDMX4(af[mt], ab + sw128((uint32_t)(row * 128 + kk * 32 + (lane >> 4) * 16)));
            }
            uint32_t bfr[2][4];
#pragma unroll
            for (int p = 0; p < 2; p++) {
                const int row = wn * 32 + p * 16 + (lane & 15);
                LDMX4(bfr[p], bb + sw128((uint32_t)(row * 128 + kk * 32 + (lane >> 4) * 16)));
            }
#pragma unroll
            for (int mt = 0; mt < 4; mt++)
#pragma unroll
                for (int nt = 0; nt < 4; nt++)
                    mma_16816(acc[mt][nt], af[mt],
                              bfr[nt >> 1][nt & 1], bfr[nt >> 1][(nt & 1) + 2]);
        }
        __syncthreads();
    }

    const int qrow = lane >> 2, qcol = (lane & 3) * 2;
#pragma unroll
    for (int mt = 0; mt < 4; mt++)
#pragma unroll
        for (int nt = 0; nt < 4; nt++)
#pragma unroll
            for (int h2 = 0; h2 < 2; h2++) {
                const int m = m0 + wm * 64 + mt * 16 + qrow + 8 * h2;
                const int n = n0 + wn * 32 + nt * 8 + qcol;
                store_proj<OMODE>(acc[mt][nt][2 * h2],     m, n,     qb, kb, f0, f1);
                store_proj<OMODE>(acc[mt][nt][2 * h2 + 1], m, n + 1, qb, kb, f0, f1);
            }
}

// ============================================================================
// Fused flash attention per head (complex, component-wise softmax).
// CTA: 64 q-rows x 16 key-blocks of 64 keys. 8 warps (2 wm x 4 wn).
//   S phase: warp tile 32x32 over S[64 x 128(2t|2t+1)], 3-pass hi/lo.
//   Online softmax (real & imag independent), P -> smem bf16 hi/lo tiles.
//   PV: O1 += pr@V, O2 += pi@V (V natural rows n=(dh,comp)), 3 passes.
// ============================================================================
__global__ void __launch_bounds__(256, 1)
fmha_kernel(const uint4* __restrict__ qb4, const uint4* __restrict__ kb4,
            const uint4* __restrict__ vb4, float2* __restrict__ out)
{
    extern __shared__ char smem[];
    const uint32_t sb0 = smem_u32(smem);
    const uint32_t sb = (sb0 + 1023) & ~1023u;
    char* smal = smem + (sb - sb0);
    const int tid = threadIdx.x;
    const int lane = tid & 31, wid = tid >> 5;
    const int wm = wid & 1, wn = wid >> 1;
    const int qrow = lane >> 2, ql = lane & 3;
    const int z = blockIdx.y;
    const int m0 = blockIdx.x * 64;

    const uint4* Qz = qb4 + ((size_t)z * 1024 + m0) * 32;   // 32 u4 / row
    const uint4* Kz = kb4 + (size_t)z * 2048 * 32;
    const uint4* Vz = vb4 + (size_t)z * 128 * 256;          // 256 u4 / row

    const uint32_t QOFF = sb;              // 4 panels x 8KB
    const uint32_t KOFF = sb + 32768;      // 2 x 16KB
    const uint32_t VOFF = sb + 65536;      // Vh 16KB | Vl 16KB
    const uint32_t POFF = sb + 98304;      // pr_hi, pi_hi, pr_lo, pi_lo x 8KB
    float2* redA = (float2*)(smal + 131072);   // [64 rows][4 wn]
    float2* redB = redA + 256;

    // --- load Q once (4 panels of 64 cols) ---
#pragma unroll
    for (int i = 0; i < 8; i++) {
        const int lin = tid + 256 * i;
        const int row = lin >> 5, u = lin & 31;
        CP_ASYNC16(QOFF + (u >> 3) * 8192 + sw128((uint32_t)(row * 128 + (u & 7) * 16)),
                   Qz + row * 32 + u);
    }
    CP_COMMIT();

    float accO1[2][4][4], accO2[2][4][4];
#pragma unroll
    for (int i = 0; i < 2; i++)
#pragma unroll
        for (int j = 0; j < 4; j++)
#pragma unroll
            for (int k = 0; k < 4; k++) { accO1[i][j][k] = 0.f; accO2[i][j][k] = 0.f; }
    float mr[2][2], mi_[2][2], lr[2][2], li[2][2];
#pragma unroll
    for (int i = 0; i < 2; i++)
#pragma unroll
        for (int j = 0; j < 2; j++) {
            mr[i][j] = -1e30f; mi_[i][j] = -1e30f; lr[i][j] = 0.f; li[i][j] = 0.f;
        }

    auto issueK = [&](int c, int kb) {
        const int colu4 = ((c >= 4) ? 16 : 0) + (c & 1) * 8;
        const uint32_t kbuf = KOFF + (c & 1) * 16384;
#pragma unroll
        for (int i = 0; i < 4; i++) {
            const int lin = tid + 256 * i;
            const int row = lin >> 3, seg = lin & 7;
            CP_ASYNC16(kbuf + sw128((uint32_t)(row * 128 + seg * 16)),
                       Kz + (size_t)(kb * 128 + row) * 32 + colu4 + seg);
        }
        CP_COMMIT();
    };

    for (int kb = 0; kb < 16; kb++) {
        // --- V (hi+lo) for this key block ---
#pragma unroll
        for (int i = 0; i < 8; i++) {
            const int lin = tid + 256 * i;
            const int half = lin >> 10, r2 = lin & 1023;
            const int row = r2 >> 3, seg = r2 & 7;
            CP_ASYNC16(VOFF + half * 16384 + sw128((uint32_t)(row * 128 + seg * 16)),
                       Vz + row * 256 + half * 128 + kb * 8 + seg);
        }
        CP_COMMIT();
        issueK(0, kb);

        float accS[2][4][4];
#pragma unroll
        for (int i = 0; i < 2; i++)
#pragma unroll
            for (int j = 0; j < 4; j++)
#pragma unroll
                for (int k = 0; k < 4; k++) accS[i][j][k] = 0.f;

        // --- S phase: 6 chunks (3 passes x 2) ---
        for (int c = 0; c < 6; c++) {
            CP_WAIT(0);
            __syncthreads();
            if (c < 5) issueK(c + 1, kb);
            const int pA = (c < 4) ? c : (c - 4);
            const uint32_t kbuf = KOFF + (c & 1) * 16384;
#pragma unroll
            for (int kk = 0; kk < 4; kk++) {
                uint32_t af[2][4], bfr[2][4];
#pragma unroll
                for (int mt = 0; mt < 2; mt++) {
                    const int row = wm * 32 + mt * 16 + (lane & 15);
                    LDMX4(af[mt], QOFF + pA * 8192 +
                          sw128((uint32_t)(row * 128 + kk * 32 + (lane >> 4) * 16)));
                }
#pragma unroll
                for (int p = 0; p < 2; p++) {
                    const int row = wn * 32 + p * 16 + (lane & 15);
                    LDMX4(bfr[p], kbuf +
                          sw128((uint32_t)(row * 128 + kk * 32 + (lane >> 4) * 16)));
                }
#pragma unroll
                for (int mt = 0; mt < 2; mt++)
#pragma unroll
                    for (int nt = 0; nt < 4; nt++)
                        mma_16816(accS[mt][nt], af[mt],
                                  bfr[nt >> 1][nt & 1], bfr[nt >> 1][(nt & 1) + 2]);
            }
        }

        // --- online softmax update ---
        constexpr float SC = 0.125f;
#pragma unroll
        for (int mt = 0; mt < 2; mt++)
#pragma unroll
            for (int h2 = 0; h2 < 2; h2++) {
                float a = fmaxf(fmaxf(accS[mt][0][2*h2], accS[mt][1][2*h2]),
                                fmaxf(accS[mt][2][2*h2], accS[mt][3][2*h2]));
                float b = fmaxf(fmaxf(accS[mt][0][2*h2+1], accS[mt][1][2*h2+1]),
                                fmaxf(accS[mt][2][2*h2+1], accS[mt][3][2*h2+1]));
                a = fmaxf(a, __shfl_xor_sync(0xffffffffu, a, 1));
                a = fmaxf(a, __shfl_xor_sync(0xffffffffu, a, 2));
                b = fmaxf(b, __shfl_xor_sync(0xffffffffu, b, 1));
                b = fmaxf(b, __shfl_xor_sync(0xffffffffu, b, 2));
                if (ql == 0)
                    redA[(wm * 32 + mt * 16 + qrow + 8 * h2) * 4 + wn] = make_float2(a, b);
            }
        __syncthreads();

        float frs[2][2], fis[2][2];
#pragma unroll
        for (int mt = 0; mt < 2; mt++)
#pragma unroll
            for (int h2 = 0; h2 < 2; h2++) {
                const int row = wm * 32 + mt * 16 + qrow + 8 * h2;
                const int ridx = row * 4;
                float2 r0 = redA[ridx], r1 = redA[ridx+1], r2v = redA[ridx+2], r3 = redA[ridx+3];
                const float bmr = fmaxf(fmaxf(r0.x, r1.x), fmaxf(r2v.x, r3.x)) * SC;
                const float bmi = fmaxf(fmaxf(r0.y, r1.y), fmaxf(r2v.y, r3.y)) * SC;
                const float nmr = fmaxf(mr[mt][h2], bmr);
                const float nmi = fmaxf(mi_[mt][h2], bmi);
                frs[mt][h2] = __expf(mr[mt][h2] - nmr);
                fis[mt][h2] = __expf(mi_[mt][h2] - nmi);
                mr[mt][h2] = nmr; mi_[mt][h2] = nmi;
#pragma unroll
                for (int nt = 0; nt < 4; nt++) {
                    accO1[mt][nt][2*h2]   *= frs[mt][h2];
                    accO1[mt][nt][2*h2+1] *= frs[mt][h2];
                    accO2[mt][nt][2*h2]   *= fis[mt][h2];
                    accO2[mt][nt][2*h2+1] *= fis[mt][h2];
                }
                float ssr = 0.f, ssi = 0.f;
#pragma unroll
                for (int nt = 0; nt < 4; nt++) {
                    const float pr = __expf(accS[mt][nt][2*h2]   * SC - nmr);
                    const float pi = __expf(accS[mt][nt][2*h2+1] * SC - nmi);
                    ssr += pr; ssi += pi;
                    const int t = wn * 16 + nt * 4 + ql;
                    const uint32_t po = sw128((uint32_t)(row * 128 + t * 2));
                    const __nv_bfloat16 phr = __float2bfloat16_rn(pr);
                    const __nv_bfloat16 plr = __float2bfloat16_rn(pr - __bfloat162float(phr));
                    const __nv_bfloat16 phi = __float2bfloat16_rn(pi);
                    const __nv_bfloat16 pli = __float2bfloat16_rn(pi - __bfloat162float(phi));
                    sts_b16(POFF +          po, phr);   // pr_hi
                    sts_b16(POFF +  8192 +  po, phi);   // pi_hi
                    sts_b16(POFF + 16384 +  po, plr);   // pr_lo
                    sts_b16(POFF + 24576 +  po, pli);   // pi_lo
                }
                ssr += __shfl_xor_sync(0xffffffffu, ssr, 1);
                ssr += __shfl_xor_sync(0xffffffffu, ssr, 2);
                ssi += __shfl_xor_sync(0xffffffffu, ssi, 1);
                ssi += __shfl_xor_sync(0xffffffffu, ssi, 2);
                if (ql == 0) redB[ridx + wn] = make_float2(ssr, ssi);
            }
        __syncthreads();

#pragma unroll
        for (int mt = 0; mt < 2; mt++)
#pragma unroll
            for (int h2 = 0; h2 < 2; h2++) {
                const int ridx = (wm * 32 + mt * 16 + qrow + 8 * h2) * 4;
                float2 r0 = redB[ridx], r1 = redB[ridx+1], r2v = redB[ridx+2], r3 = redB[ridx+3];
                lr[mt][h2] = lr[mt][h2] * frs[mt][h2] + (r0.x + r1.x + r2v.x + r3.x);
                li[mt][h2] = li[mt][h2] * fis[mt][h2] + (r0.y + r1.y + r2v.y + r3.y);
            }

        // --- PV: 3 passes (ph@Vh, pl@Vh, ph@Vl) into O1 (pr) and O2 (pi) ---
#pragma unroll
        for (int pass = 0; pass < 3; pass++) {
            const uint32_t pbase = POFF + ((pass == 1) ? 16384 : 0);
            const uint32_t vbase = VOFF + ((pass == 2) ? 16384 : 0);
#pragma unroll
            for (int kk = 0; kk < 4; kk++) {
                uint32_t a1[2][4], a2[2][4], bfr[2][4];
#pragma unroll
                for (int mt = 0; mt < 2; mt++) {
                    const int row = wm * 32 + mt * 16 + (lane & 15);
                    const uint32_t off =
                        sw128((uint32_t)(row * 128 + kk * 32 + (lane >> 4) * 16));
                    LDMX4(a1[mt], pbase + off);
                    LDMX4(a2[mt], pbase + 8192 + off);
                }
#pragma unroll
                for (int p = 0; p < 2; p++) {
                    const int row = wn * 32 + p * 16 + (lane & 15);
                    LDMX4(bfr[p], vbase +
                          sw128((uint32_t)(row * 128 + kk * 32 + (lane >> 4) * 16)));
                }
#pragma unroll
                for (int mt = 0; mt < 2; mt++)
#pragma unroll
                    for (int nt = 0; nt < 4; nt++) {
                        mma_16816(accO1[mt][nt], a1[mt],
                                  bfr[nt >> 1][nt & 1], bfr[nt >> 1][(nt & 1) + 2]);
                        mma_16816(accO2[mt][nt], a2[mt],
                                  bfr[nt >> 1][nt & 1], bfr[nt >> 1][(nt & 1) + 2]);
                    }
            }
        }
        __syncthreads();   // protect P/V smem for next block
    }

    // --- epilogue: combine and normalize ---
#pragma unroll
    for (int mt = 0; mt < 2; mt++)
#pragma unroll
        for (int h2 = 0; h2 < 2; h2++) {
            const float ivr = 1.f / lr[mt][h2];
            const float ivi = 1.f / li[mt][h2];
            const int s = m0 + wm * 32 + mt * 16 + qrow + 8 * h2;
#pragma unroll
            for (int nt = 0; nt < 4; nt++) {
                const int dh = wn * 16 + nt * 4 + ql;
                const float o_r = accO1[mt][nt][2*h2]   * ivr - accO2[mt][nt][2*h2+1] * ivi;
                const float o_i = accO1[mt][nt][2*h2+1] * ivr + accO2[mt][nt][2*h2]   * ivi;
                out[(((size_t)(z >> 3) * 1024 + s) * 512) + (z & 7) * 64 + dh] =
                    make_float2(o_r, o_i);
            }
        }
}

// ============================================================================
// V operand: planar fp32 [z][s][dh] -> g_vb [z][n=128][2048]
//   n=2dh -> vr(t), n=2dh+1 -> vi(t); hi cols [0,1024), lo [1024,2048)
// ============================================================================
__global__ void __launch_bounds__(256)
vconv_kernel(const float* __restrict__ vr, const float* __restrict__ vi,
             __nv_bfloat16* __restrict__ vb)
{
    __shared__ float tile[2][64][65];
    const int z = blockIdx.y, s0 = blockIdx.x * 64;
    const int tid = threadIdx.x;
#pragma unroll
    for (int i = 0; i < 16; i++) {
        const int idx = tid + 256 * i;
        const int row = idx >> 6, c = idx & 63;
        const size_t g = ((size_t)z * 1024 + s0 + row) * 64 + c;
        tile[0][row][c] = vr[g];
        tile[1][row][c] = vi[g];
    }
    __syncthreads();
    const int r = tid >> 1, h4 = tid & 1;
    const int dh = r >> 1, ci = r & 1;
    __nv_bfloat16 hb[32], lb[32];
#pragma unroll
    for (int j = 0; j < 32; j++) {
        const int t = h4 * 32 + j;
        const float v = ci ? tile[1][t][dh] : tile[0][t][dh];
        const __nv_bfloat16 h = __float2bfloat16_rn(v);
        hb[j] = h;
        lb[j] = __float2bfloat16_rn(v - __bfloat162float(h));
    }
    const size_t base = ((size_t)z * 128 + r) * 2048 + s0 + h4 * 32;
#pragma unroll
    for (int u = 0; u < 4; u++) {
        *(uint4*)(vb + base + 8 * u) = pack8(hb + 8 * u);
        *(uint4*)(vb + base + 1024 + 8 * u) = pack8(lb + 8 * u);
    }
}

// ============================================================================
// fp32 -> bf16 hi/lo conversions for projections
// ============================================================================
__global__ void __launch_bounds__(256)
convx_kernel(const float2* __restrict__ in, __nv_bfloat16* __restrict__ out)
{
    const int idx = blockIdx.x * 256 + threadIdx.x;
    const int m = idx >> 7;
    const int comp = (idx >> 6) & 1;
    const int f8 = (idx & 63) * 8;
    const float2* src = in + (long long)m * 512 + f8;
    __nv_bfloat16 hi[8], lo[8];
#pragma unroll
    for (int j = 0; j < 8; j++) {
        const float x = comp ? src[j].y : src[j].x;
        const __nv_bfloat16 h = __float2bfloat16_rn(x);
        hi[j] = h;
        lo[j] = __float2bfloat16_rn(x - __bfloat162float(h));
    }
    __nv_bfloat16* dst = out + (long long)m * 2048 + comp * 512 + f8;
    *(uint4*)dst = pack8(hi);
    *(uint4*)(dst + 1024) = pack8(lo);
}

__global__ void __launch_bounds__(256)
convw_kernel(const float* __restrict__ wr, const float* __restrict__ wi,
             __nv_bfloat16* __restrict__ out)
{
    const int idx = blockIdx.x * 256 + threadIdx.x;
    const int n = idx >> 7;
    const int half = (idx >> 6) & 1;
    const int f8 = (idx & 63) * 8;
    const float* src;
    float sgn = 1.f;
    if (n < 512) { src = (half ? wi : wr) + (long long)n * 512; if (half) sgn = -1.f; }
    else         { src = (half ? wr : wi) + (long long)(n - 512) * 512; }
    __nv_bfloat16 hi[8], lo[8];
#pragma unroll
    for (int j = 0; j < 8; j++) {
        const float x = sgn * src[f8 + j];
        const __nv_bfloat16 h = __float2bfloat16_rn(x);
        hi[j] = h;
        lo[j] = __float2bfloat16_rn(x - __bfloat162float(h));
    }
    __nv_bfloat16* dst = out + (long long)n * 2048 + half * 512 + f8;
    *(uint4*)dst = pack8(hi);
    *(uint4*)(dst + 1024) = pack8(lo);
}

// ============================================================================
extern "C" void kernel_launch(void* const* d_in, const int* in_sizes, int n_in,
                              void* d_out, int out_size)
{
    (void)in_sizes; (void)n_in; (void)out_size;
    const float2* Qin = (const float2*)d_in[0];
    const float2* Kin = (const float2*)d_in[1];
    const float2* Vin = (const float2*)d_in[2];
    const float* wq_r = (const float*)d_in[3];
    const float* wq_i = (const float*)d_in[4];
    const float* wk_r = (const float*)d_in[5];
    const float* wk_i = (const float*)d_in[6];
    const float* wv_r = (const float*)d_in[7];
    const float* wv_i = (const float*)d_in[8];
    const float* wo_r = (const float*)d_in[9];
    const float* wo_i = (const float*)d_in[10];

    float *vr, *vi;
    float2 *o;
    __nv_bfloat16 *x2, *w2, *qb, *kb, *vb;
    cudaGetSymbolAddress((void**)&vr, g_vr);
    cudaGetSymbolAddress((void**)&vi, g_vi);
    cudaGetSymbolAddress((void**)&o, g_o);
    cudaGetSymbolAddress((void**)&x2, g_x2);
    cudaGetSymbolAddress((void**)&w2, g_w2);
    cudaGetSymbolAddress((void**)&qb, g_qb);
    cudaGetSymbolAddress((void**)&kb, g_kb);
    cudaGetSymbolAddress((void**)&vb, g_vb);

    cudaFuncSetAttribute(tgemm_kernel<0>, cudaFuncAttributeMaxDynamicSharedMemorySize, SM_TOTAL);
    cudaFuncSetAttribute(tgemm_kernel<1>, cudaFuncAttributeMaxDynamicSharedMemorySize, SM_TOTAL);
    cudaFuncSetAttribute(tgemm_kernel<2>, cudaFuncAttributeMaxDynamicSharedMemorySize, SM_TOTAL);
    cudaFuncSetAttribute(tgemm_kernel<3>, cudaFuncAttributeMaxDynamicSharedMemorySize, SM_TOTAL);
    cudaFuncSetAttribute(fmha_kernel, cudaFuncAttributeMaxDynamicSharedMemorySize, SMF_TOTAL);

    const dim3 gt(8, 64);
    const uint4* x4 = (const uint4*)x2;
    const uint4* w4 = (const uint4*)w2;

    // --- projections ---
    convx_kernel<<<4096, 256>>>(Qin, x2);
    convw_kernel<<<512, 256>>>(wq_r, wq_i, w2);
    tgemm_kernel<0><<<gt, 256, SM_TOTAL>>>(x4, w4, nullptr, nullptr, qb, nullptr);
    convx_kernel<<<4096, 256>>>(Kin, x2);
    convw_kernel<<<512, 256>>>(wk_r, wk_i, w2);
    tgemm_kernel<1><<<gt, 256, SM_TOTAL>>>(x4, w4, nullptr, nullptr, nullptr, kb);
    convx_kernel<<<4096, 256>>>(Vin, x2);
    convw_kernel<<<512, 256>>>(wv_r, wv_i, w2);
    tgemm_kernel<2><<<gt, 256, SM_TOTAL>>>(x4, w4, vr, vi, nullptr, nullptr);
    vconv_kernel<<<dim3(16, 64), 256>>>(vr, vi, vb);

    // --- fused attention (scores + softmax + PV) ---
    fmha_kernel<<<dim3(16, 64), 256, SMF_TOTAL>>>(
        (const uint4*)qb, (const uint4*)kb, (const uint4*)vb, o);

    // --- output projection ---
    convx_kernel<<<4096, 256>>>(o, x2);
    convw_kernel<<<512, 256>>>(wo_r, wo_i, w2);
    tgemm_kernel<3><<<gt, 256, SM_TOTAL>>>(x4, w4, (float*)d_out, nullptr, nullptr, nullptr);
}

// round 8
// speedup vs baseline: 1.8752x; 1.0271x over previous
#include <cuda_runtime.h>
#include <cuda_bf16.h>
#include <cstdint>

// ============================================================================
// Problem constants
// ============================================================================
namespace {
constexpr int Bn = 8;
constexpr int Sn = 1024;
constexpr int Dn = 512;
constexpr int Hn = 8;
constexpr int Mproj = Bn * Sn;                                   // 8192

__device__ float g_vr[(long long)Bn * Hn * Sn * 64];    // planar V fp32
__device__ float g_vi[(long long)Bn * Hn * Sn * 64];
__device__ float2 g_o[(long long)Bn * Sn * Dn];         // attn out [B,S,D]
__device__ __nv_bfloat16 g_x2[(long long)Mproj * 2048]; // act hi|lo for proj
__device__ __nv_bfloat16 g_w2[(long long)1024 * 2048];  // wgt hi|lo for proj
__device__ __nv_bfloat16 g_qb[(long long)64 * 1024 * 256];  // Q score-operand
__device__ __nv_bfloat16 g_kb[(long long)64 * 2048 * 256];  // K: re rows | im rows
__device__ __nv_bfloat16 g_vb[(long long)64 * 128 * 2048];  // V natural operand
}

// ============================================================================
// Base-target PTX helpers
// ============================================================================
__device__ __forceinline__ uint32_t smem_u32(const void* p) {
    uint32_t a;
    asm("{ .reg .u64 t; cvta.to.shared.u64 t, %1; cvt.u32.u64 %0, t; }"
        : "=r"(a) : "l"(p));
    return a;
}
__device__ __forceinline__ uint32_t sw128(uint32_t off) {
    return off ^ ((off >> 3) & 0x70);
}
#define LDMX4(r, addr)                                                        \
    asm volatile("ldmatrix.sync.aligned.m8n8.x4.shared.b16 {%0,%1,%2,%3}, [%4];" \
        : "=r"((r)[0]), "=r"((r)[1]), "=r"((r)[2]), "=r"((r)[3]) : "r"(addr))
__device__ __forceinline__ void mma_16816(float* d, const uint32_t* a,
                                          uint32_t b0, uint32_t b1) {
    asm volatile(
        "mma.sync.aligned.m16n8k16.row.col.f32.bf16.bf16.f32 "
        "{%0,%1,%2,%3}, {%4,%5,%6,%7}, {%8,%9}, {%0,%1,%2,%3};"
        : "+f"(d[0]), "+f"(d[1]), "+f"(d[2]), "+f"(d[3])
        : "r"(a[0]), "r"(a[1]), "r"(a[2]), "r"(a[3]), "r"(b0), "r"(b1));
}
#define CP_ASYNC16(dst, src) \
    asm volatile("cp.async.cg.shared.global [%0], [%1], 16;" :: "r"(dst), "l"(src))
#define CP_COMMIT()     asm volatile("cp.async.commit_group;" ::: "memory")
#define CP_WAIT(n)      asm volatile("cp.async.wait_group %0;" :: "n"(n) : "memory")

namespace {
constexpr int SM_BUF = 32768;
constexpr int SM_TOTAL = 2 * SM_BUF + 1024;
constexpr int SMF_TOTAL = 131072 + 1024;   // Q 64K + K 32K + V 32K + align
}

__device__ __forceinline__ uint4 pack8(const __nv_bfloat16* v) {
    union { __nv_bfloat16 b[8]; uint4 u; } P;
#pragma unroll
    for (int i = 0; i < 8; i++) P.b[i] = v[i];
    return P.u;
}
__device__ __forceinline__ uint32_t pack2(float x, float y, float& lx, float& ly) {
    __nv_bfloat16 hx = __float2bfloat16_rn(x);
    __nv_bfloat16 hy = __float2bfloat16_rn(y);
    lx = x - __bfloat162float(hx);
    ly = y - __bfloat162float(hy);
    unsigned short ux = *reinterpret_cast<unsigned short*>(&hx);
    unsigned short uy = *reinterpret_cast<unsigned short*>(&hy);
    return (uint32_t)ux | ((uint32_t)uy << 16);
}
__device__ __forceinline__ uint32_t pack2n(float x, float y) {
    __nv_bfloat16 hx = __float2bfloat16_rn(x);
    __nv_bfloat16 hy = __float2bfloat16_rn(y);
    unsigned short ux = *reinterpret_cast<unsigned short*>(&hx);
    unsigned short uy = *reinterpret_cast<unsigned short*>(&hy);
    return (uint32_t)ux | ((uint32_t)uy << 16);
}

// ============================================================================
// Projection GEMM (proven engine): C = X2 x W2^T, bf16 hi/lo 3-pass.
//   OMODE 0: Q -> g_qb; 1: K -> g_kb (re rows | im rows); 2: V planar; 3: d_out
// ============================================================================
template<int OMODE>
__device__ __forceinline__ void store_proj(float v, int m, int n,
    __nv_bfloat16* qb, __nv_bfloat16* kb, float* f0, float* f1)
{
    const int comp = n >> 9, f = n & 511, hh = f >> 6, dh = f & 63;
    if (OMODE == 3) {
        f0[(size_t)m * 1024 + (size_t)f * 2 + comp] = v;
        return;
    }
    const int z = ((m >> 10) << 3) + hh;
    const int s = m & 1023;
    if (OMODE == 2) {
        (comp ? f1 : f0)[((size_t)z * 1024 + s) * 64 + dh] = v;
        return;
    }
    const __nv_bfloat16 h = __float2bfloat16_rn(v);
    const __nv_bfloat16 l = __float2bfloat16_rn(v - __bfloat162float(h));
    if (OMODE == 0) {
        const size_t base = ((size_t)z * 1024 + s) * 256 + comp * 64 + dh;
        qb[base] = h; qb[base + 128] = l;
    } else {
        // real form at row s, imag form at row 1024+s
        const size_t r0 = ((size_t)z * 2048 + s) * 256;
        const size_t r1 = ((size_t)z * 2048 + 1024 + s) * 256;
        if (comp == 0) {
            kb[r0 + dh] = h;       kb[r0 + 128 + dh] = l;
            kb[r1 + 64 + dh] = h;  kb[r1 + 192 + dh] = l;
        } else {
            kb[r0 + 64 + dh] = __hneg(h); kb[r0 + 192 + dh] = __hneg(l);
            kb[r1 + dh] = h;       kb[r1 + 128 + dh] = l;
        }
    }
}

template<int OMODE>
__global__ void __launch_bounds__(256, 1)
tgemm_kernel(const uint4* __restrict__ A2, const uint4* __restrict__ B2,
             float* __restrict__ f0, float* __restrict__ f1,
             __nv_bfloat16* __restrict__ qb, __nv_bfloat16* __restrict__ kb)
{
    extern __shared__ char smem[];
    const uint32_t sbase = (smem_u32(smem) + 1023) & ~1023u;
    const int tid = threadIdx.x;
    const int lane = tid & 31, wid = tid >> 5;
    const int wm = wid & 1, wn = wid >> 1;
    const int m0 = blockIdx.y * 128, n0 = blockIdx.x * 128;

    float acc[4][4][4];
#pragma unroll
    for (int i = 0; i < 4; i++)
#pragma unroll
        for (int j = 0; j < 4; j++)
#pragma unroll
            for (int k = 0; k < 4; k++) acc[i][j][k] = 0.f;

    auto issue_chunk = [&](int c, int buf) {
        const int pass = c >> 4;
        const int kc = (c & 15) << 6;
        const int ca = (kc + ((pass == 1) ? 1024 : 0)) >> 3;
        const int cb = (kc + ((pass == 2) ? 1024 : 0)) >> 3;
        const uint32_t ab = sbase + buf * SM_BUF;
        const uint32_t bb = ab + 16384;
#pragma unroll
        for (int i = 0; i < 4; i++) {
            const int lin = tid + 256 * i;
            const int row = lin >> 3, seg = lin & 7;
            const uint32_t off = sw128((uint32_t)(row * 128 + seg * 16));
            CP_ASYNC16(ab + off, &A2[(size_t)(m0 + row) * 256 + ca + seg]);
            CP_ASYNC16(bb + off, &B2[(size_t)(n0 + row) * 256 + cb + seg]);
        }
        CP_COMMIT();
    };

    constexpr int NC = 48;
    issue_chunk(0, 0);
    for (int c = 0; c < NC; c++) {
        const int buf = c & 1;
        if (c + 1 < NC) { issue_chunk(c + 1, buf ^ 1); CP_WAIT(1); }
        else            { CP_WAIT(0); }
        __syncthreads();
        const uint32_t ab = sbase + buf * SM_BUF;
        const uint32_t bb = ab + 16384;
#pragma unroll
        for (int kk = 0; kk < 4; kk++) {
            uint32_t af[4][4];
#pragma unroll
            for (int mt = 0; mt < 4; mt++) {
                const int row = wm * 64 + mt * 16 + (lane & 15);
                LDMX4(af[mt], ab + sw128((uint32_t)(row * 128 + kk * 32 + (lane >> 4) * 16)));
            }
            uint32_t bfr[2][4];
#pragma unroll
            for (int p = 0; p < 2; p++) {
                const int row = wn * 32 + p * 16 + (lane & 15);
                LDMX4(bfr[p], bb + sw128((uint32_t)(row * 128 + kk * 32 + (lane >> 4) * 16)));
            }
#pragma unroll
            for (int mt = 0; mt < 4; mt++)
#pragma unroll
                for (int nt = 0; nt < 4; nt++)
                    mma_16816(acc[mt][nt], af[mt],
                              bfr[nt >> 1][nt & 1], bfr[nt >> 1][(nt & 1) + 2]);
        }
        __syncthreads();
    }

    const int qrow = lane >> 2, qcol = (lane & 3) * 2;
#pragma unroll
    for (int mt = 0; mt < 4; mt++)
#pragma unroll
        for (int nt = 0; nt < 4; nt++)
#pragma unroll
            for (int h2 = 0; h2 < 2; h2++) {
                const int m = m0 + wm * 64 + mt * 16 + qrow + 8 * h2;
                const int n = n0 + wn * 32 + nt * 8 + qcol;
                store_proj<OMODE>(acc[mt][nt][2 * h2],     m, n,     qb, kb, f0, f1);
                store_proj<OMODE>(acc[mt][nt][2 * h2 + 1], m, n + 1, qb, kb, f0, f1);
            }
}

// ============================================================================
// Fused flash attention, register-resident P.
// CTA: 128 q-rows x 1 head; 8 warps, warp w owns rows 16w..16w+16.
// S-cols per key-block: [s_r keys 0..63 | s_i keys 0..63].
// A-frag register order: a0=(r,k), a1=(r+8,k), a2=(r,k+8), a3=(r+8,k+8).
// ============================================================================
__global__ void __launch_bounds__(256, 1)
fmha_kernel(const uint4* __restrict__ qb4, const uint4* __restrict__ kb4,
            const uint4* __restrict__ vb4, float2* __restrict__ out)
{
    extern __shared__ char smem[];
    const uint32_t sb = (smem_u32(smem) + 1023) & ~1023u;
    const int tid = threadIdx.x;
    const int lane = tid & 31, w = tid >> 5;
    const int qrow = lane >> 2, ql = lane & 3;
    const int z = blockIdx.y;
    const int m0 = blockIdx.x * 128;

    const uint4* Qz = qb4 + ((size_t)z * 1024 + m0) * 32;
    const uint4* Kz = kb4 + (size_t)z * 2048 * 32;
    const uint4* Vz = vb4 + (size_t)z * 128 * 256;

    const uint32_t QOFF = sb;                 // 4 panels x 16KB
    const uint32_t KOFF = sb + 65536;         // 2 x 16KB
    const uint32_t VOFF = sb + 98304;         // Vh 16KB | Vl 16KB

    // --- Q load (128 rows x 256 cols; 4 panels of 64 cols) ---
#pragma unroll
    for (int i = 0; i < 16; i++) {
        const int lin = tid + 256 * i;
        const int row = lin >> 5, u = lin & 31;
        CP_ASYNC16(QOFF + (u >> 3) * 16384 + sw128((uint32_t)(row * 128 + (u & 7) * 16)),
                   Qz + row * 32 + u);
    }
    CP_COMMIT();

    float accO1[16][4], accO2[16][4];
#pragma unroll
    for (int i = 0; i < 16; i++)
#pragma unroll
        for (int j = 0; j < 4; j++) { accO1[i][j] = 0.f; accO2[i][j] = 0.f; }
    float mr[2] = {-1e30f, -1e30f}, mi_[2] = {-1e30f, -1e30f};
    float lr[2] = {0.f, 0.f}, li[2] = {0.f, 0.f};

    auto issueK = [&](int c, int kb) {
        const int g = (c < 4) ? (c & 1) : (c - 2);   // K col group
        const uint32_t kbuf = KOFF + (c & 1) * 16384;
#pragma unroll
        for (int i = 0; i < 4; i++) {
            const int lin = tid + 256 * i;           // 0..1023
            const int row = lin >> 3, seg = lin & 7; // row 0..127
            const int grow = kb * 64 + (row & 63) + ((row >> 6) << 10);
            CP_ASYNC16(kbuf + sw128((uint32_t)(row * 128 + seg * 16)),
                       Kz + (size_t)grow * 32 + g * 8 + seg);
        }
        CP_COMMIT();
    };

    constexpr float SC = 0.125f;

    for (int kb = 0; kb < 16; kb++) {
        // V (hi+lo halves) for this key block
#pragma unroll
        for (int i = 0; i < 8; i++) {
            const int lin = tid + 256 * i;           // 0..2047
            const int half = lin >> 10, r2 = lin & 1023;
            const int row = r2 >> 3, seg = r2 & 7;
            CP_ASYNC16(VOFF + half * 16384 + sw128((uint32_t)(row * 128 + seg * 16)),
                       Vz + row * 256 + half * 128 + kb * 8 + seg);
        }
        CP_COMMIT();
        issueK(0, kb);

        float accS[16][4];
#pragma unroll
        for (int i = 0; i < 16; i++)
#pragma unroll
            for (int j = 0; j < 4; j++) accS[i][j] = 0.f;

        // --- S phase: 6 chunks (3 hi/lo passes x 2 col-halves) ---
        for (int c = 0; c < 6; c++) {
            CP_WAIT(0);
            __syncthreads();
            if (c < 5) issueK(c + 1, kb);
            const int pA = (c < 4) ? c : (c - 4);
            const uint32_t kbuf = KOFF + (c & 1) * 16384;
            const uint32_t qbase = QOFF + pA * 16384;
#pragma unroll
            for (int kk = 0; kk < 4; kk++) {
                uint32_t af[4];
                LDMX4(af, qbase + sw128((uint32_t)((16 * w + (lane & 15)) * 128
                                                   + kk * 32 + (lane >> 4) * 16)));
#pragma unroll
                for (int ntp = 0; ntp < 8; ntp++) {
                    uint32_t bfr[4];
                    LDMX4(bfr, kbuf + sw128((uint32_t)((ntp * 16 + (lane & 15)) * 128
                                                       + kk * 32 + (lane >> 4) * 16)));
                    mma_16816(accS[2 * ntp],     af, bfr[0], bfr[2]);
                    mma_16816(accS[2 * ntp + 1], af, bfr[1], bfr[3]);
                }
            }
        }

        // --- warp-local online softmax ---
        float fr[2], fi[2];
#pragma unroll
        for (int g2 = 0; g2 < 2; g2++) {
            float a = -1e30f, b = -1e30f;
#pragma unroll
            for (int nt = 0; nt < 8; nt++) {
                a = fmaxf(a, fmaxf(accS[nt][2 * g2], accS[nt][2 * g2 + 1]));
                b = fmaxf(b, fmaxf(accS[nt + 8][2 * g2], accS[nt + 8][2 * g2 + 1]));
            }
            a = fmaxf(a, __shfl_xor_sync(0xffffffffu, a, 1));
            a = fmaxf(a, __shfl_xor_sync(0xffffffffu, a, 2));
            b = fmaxf(b, __shfl_xor_sync(0xffffffffu, b, 1));
            b = fmaxf(b, __shfl_xor_sync(0xffffffffu, b, 2));
            a *= SC; b *= SC;
            const float nmr = fmaxf(mr[g2], a);
            const float nmi = fmaxf(mi_[g2], b);
            fr[g2] = __expf(mr[g2] - nmr);
            fi[g2] = __expf(mi_[g2] - nmi);
            mr[g2] = nmr; mi_[g2] = nmi;
        }
#pragma unroll
        for (int nt = 0; nt < 16; nt++) {
            accO1[nt][0] *= fr[0]; accO1[nt][1] *= fr[0];
            accO1[nt][2] *= fr[1]; accO1[nt][3] *= fr[1];
            accO2[nt][0] *= fi[0]; accO2[nt][1] *= fi[0];
            accO2[nt][2] *= fi[1]; accO2[nt][3] *= fi[1];
        }

        // --- pack P (C-frag -> A-frag, row-half fastest) + PV Vh pass ---
        uint32_t prh[4][4], pih[4][4];
        float sr0 = 0.f, sr1 = 0.f, si0 = 0.f, si1 = 0.f;
#pragma unroll
        for (int kk2 = 0; kk2 < 4; kk2++) {
            uint32_t prl[4], pil[4];
#pragma unroll
            for (int half = 0; half < 2; half++) {   // half = k-subtile (8 keys)
                {
                    const int nt = 2 * kk2 + half;
                    const float p0 = __expf(accS[nt][0] * SC - mr[0]);
                    const float p1 = __expf(accS[nt][1] * SC - mr[0]);
                    const float p2 = __expf(accS[nt][2] * SC - mr[1]);
                    const float p3 = __expf(accS[nt][3] * SC - mr[1]);
                    sr0 += p0 + p1; sr1 += p2 + p3;
                    float l0, l1, l2, l3;
                    // a-frag order: [2*half] = row r, [2*half+1] = row r+8
                    prh[kk2][2 * half]     = pack2(p0, p1, l0, l1);
                    prh[kk2][2 * half + 1] = pack2(p2, p3, l2, l3);
                    prl[2 * half]          = pack2n(l0, l1);
                    prl[2 * half + 1]      = pack2n(l2, l3);
                }
                {
                    const int nt = 8 + 2 * kk2 + half;
                    const float p0 = __expf(accS[nt][0] * SC - mi_[0]);
                    const float p1 = __expf(accS[nt][1] * SC - mi_[0]);
                    const float p2 = __expf(accS[nt][2] * SC - mi_[1]);
                    const float p3 = __expf(accS[nt][3] * SC - mi_[1]);
                    si0 += p0 + p1; si1 += p2 + p3;
                    float l0, l1, l2, l3;
                    pih[kk2][2 * half]     = pack2(p0, p1, l0, l1);
                    pih[kk2][2 * half + 1] = pack2(p2, p3, l2, l3);
                    pil[2 * half]          = pack2n(l0, l1);
                    pil[2 * half + 1]      = pack2n(l2, l3);
                }
            }
            // PV against Vh for this k-step: ph + pl
#pragma unroll
            for (int ntp = 0; ntp < 8; ntp++) {
                uint32_t bfr[4];
                LDMX4(bfr, VOFF + sw128((uint32_t)((ntp * 16 + (lane & 15)) * 128
                                                   + kk2 * 32 + (lane >> 4) * 16)));
                mma_16816(accO1[2 * ntp],     prh[kk2], bfr[0], bfr[2]);
                mma_16816(accO1[2 * ntp + 1], prh[kk2], bfr[1], bfr[3]);
                mma_16816(accO1[2 * ntp],     prl,      bfr[0], bfr[2]);
                mma_16816(accO1[2 * ntp + 1], prl,      bfr[1], bfr[3]);
                mma_16816(accO2[2 * ntp],     pih[kk2], bfr[0], bfr[2]);
                mma_16816(accO2[2 * ntp + 1], pih[kk2], bfr[1], bfr[3]);
                mma_16816(accO2[2 * ntp],     pil,      bfr[0], bfr[2]);
                mma_16816(accO2[2 * ntp + 1], pil,      bfr[1], bfr[3]);
            }
        }
        // row-sum reduce + running l update
        sr0 += __shfl_xor_sync(0xffffffffu, sr0, 1);
        sr0 += __shfl_xor_sync(0xffffffffu, sr0, 2);
        sr1 += __shfl_xor_sync(0xffffffffu, sr1, 1);
        sr1 += __shfl_xor_sync(0xffffffffu, sr1, 2);
        si0 += __shfl_xor_sync(0xffffffffu, si0, 1);
        si0 += __shfl_xor_sync(0xffffffffu, si0, 2);
        si1 += __shfl_xor_sync(0xffffffffu, si1, 1);
        si1 += __shfl_xor_sync(0xffffffffu, si1, 2);
        lr[0] = lr[0] * fr[0] + sr0;  lr[1] = lr[1] * fr[1] + sr1;
        li[0] = li[0] * fi[0] + si0;  li[1] = li[1] * fi[1] + si1;

        // --- PV Vl pass (ph only) ---
#pragma unroll
        for (int kk2 = 0; kk2 < 4; kk2++)
#pragma unroll
            for (int ntp = 0; ntp < 8; ntp++) {
                uint32_t bfr[4];
                LDMX4(bfr, VOFF + 16384 + sw128((uint32_t)((ntp * 16 + (lane & 15)) * 128
                                                           + kk2 * 32 + (lane >> 4) * 16)));
                mma_16816(accO1[2 * ntp],     prh[kk2], bfr[0], bfr[2]);
                mma_16816(accO1[2 * ntp + 1], prh[kk2], bfr[1], bfr[3]);
                mma_16816(accO2[2 * ntp],     pih[kk2], bfr[0], bfr[2]);
                mma_16816(accO2[2 * ntp + 1], pih[kk2], bfr[1], bfr[3]);
            }

        __syncthreads();   // protect K/V smem before next block's loads
    }

    // --- epilogue: combine components, normalize, store ---
#pragma unroll
    for (int g2 = 0; g2 < 2; g2++) {
        const float ivr = 1.f / lr[g2];
        const float ivi = 1.f / li[g2];
        const int s = m0 + 16 * w + qrow + 8 * g2;
#pragma unroll
        for (int nt = 0; nt < 16; nt++) {
            const int dh = 4 * nt + ql;
            const float o_r = accO1[nt][2 * g2]     * ivr - accO2[nt][2 * g2 + 1] * ivi;
            const float o_i = accO1[nt][2 * g2 + 1] * ivr + accO2[nt][2 * g2]     * ivi;
            out[((size_t)(z >> 3) * 1024 + s) * 512 + (z & 7) * 64 + dh] =
                make_float2(o_r, o_i);
        }
    }
}

// ============================================================================
// V operand: planar fp32 [z][s][dh] -> g_vb [z][n=128][2048]
// ============================================================================
__global__ void __launch_bounds__(256)
vconv_kernel(const float* __restrict__ vr, const float* __restrict__ vi,
             __nv_bfloat16* __restrict__ vb)
{
    __shared__ float tile[2][64][65];
    const int z = blockIdx.y, s0 = blockIdx.x * 64;
    const int tid = threadIdx.x;
#pragma unroll
    for (int i = 0; i < 16; i++) {
        const int idx = tid + 256 * i;
        const int row = idx >> 6, c = idx & 63;
        const size_t g = ((size_t)z * 1024 + s0 + row) * 64 + c;
        tile[0][row][c] = vr[g];
        tile[1][row][c] = vi[g];
    }
    __syncthreads();
    const int r = tid >> 1, h4 = tid & 1;
    const int dh = r >> 1, ci = r & 1;
    __nv_bfloat16 hb[32], lb[32];
#pragma unroll
    for (int j = 0; j < 32; j++) {
        const int t = h4 * 32 + j;
        const float v = ci ? tile[1][t][dh] : tile[0][t][dh];
        const __nv_bfloat16 h = __float2bfloat16_rn(v);
        hb[j] = h;
        lb[j] = __float2bfloat16_rn(v - __bfloat162float(h));
    }
    const size_t base = ((size_t)z * 128 + r) * 2048 + s0 + h4 * 32;
#pragma unroll
    for (int u = 0; u < 4; u++) {
        *(uint4*)(vb + base + 8 * u) = pack8(hb + 8 * u);
        *(uint4*)(vb + base + 1024 + 8 * u) = pack8(lb + 8 * u);
    }
}

// ============================================================================
// fp32 -> bf16 hi/lo conversions
// ============================================================================
__global__ void __launch_bounds__(256)
convx_kernel(const float2* __restrict__ in, __nv_bfloat16* __restrict__ out)
{
    const int idx = blockIdx.x * 256 + threadIdx.x;
    const int m = idx >> 7;
    const int comp = (idx >> 6) & 1;
    const int f8 = (idx & 63) * 8;
    const float2* src = in + (long long)m * 512 + f8;
    __nv_bfloat16 hi[8], lo[8];
#pragma unroll
    for (int j = 0; j < 8; j++) {
        const float x = comp ? src[j].y : src[j].x;
        const __nv_bfloat16 h = __float2bfloat16_rn(x);
        hi[j] = h;
        lo[j] = __float2bfloat16_rn(x - __bfloat162float(h));
    }
    __nv_bfloat16* dst = out + (long long)m * 2048 + comp * 512 + f8;
    *(uint4*)dst = pack8(hi);
    *(uint4*)(dst + 1024) = pack8(lo);
}

__global__ void __launch_bounds__(256)
convw_kernel(const float* __restrict__ wr, const float* __restrict__ wi,
             __nv_bfloat16* __restrict__ out)
{
    const int idx = blockIdx.x * 256 + threadIdx.x;
    const int n = idx >> 7;
    const int half = (idx >> 6) & 1;
    const int f8 = (idx & 63) * 8;
    const float* src;
    float sgn = 1.f;
    if (n < 512) { src = (half ? wi : wr) + (long long)n * 512; if (half) sgn = -1.f; }
    else         { src = (half ? wr : wi) + (long long)(n - 512) * 512; }
    __nv_bfloat16 hi[8], lo[8];
#pragma unroll
    for (int j = 0; j < 8; j++) {
        const float x = sgn * src[f8 + j];
        const __nv_bfloat16 h = __float2bfloat16_rn(x);
        hi[j] = h;
        lo[j] = __float2bfloat16_rn(x - __bfloat162float(h));
    }
    __nv_bfloat16* dst = out + (long long)n * 2048 + half * 512 + f8;
    *(uint4*)dst = pack8(hi);
    *(uint4*)(dst + 1024) = pack8(lo);
}

// ============================================================================
extern "C" void kernel_launch(void* const* d_in, const int* in_sizes, int n_in,
                              void* d_out, int out_size)
{
    (void)in_sizes; (void)n_in; (void)out_size;
    const float2* Qin = (const float2*)d_in[0];
    const float2* Kin = (const float2*)d_in[1];
    const float2* Vin = (const float2*)d_in[2];
    const float* wq_r = (const float*)d_in[3];
    const float* wq_i = (const float*)d_in[4];
    const float* wk_r = (const float*)d_in[5];
    const float* wk_i = (const float*)d_in[6];
    const float* wv_r = (const float*)d_in[7];
    const float* wv_i = (const float*)d_in[8];
    const float* wo_r = (const float*)d_in[9];
    const float* wo_i = (const float*)d_in[10];

    float *vr, *vi;
    float2 *o;
    __nv_bfloat16 *x2, *w2, *qb, *kb, *vb;
    cudaGetSymbolAddress((void**)&vr, g_vr);
    cudaGetSymbolAddress((void**)&vi, g_vi);
    cudaGetSymbolAddress((void**)&o, g_o);
    cudaGetSymbolAddress((void**)&x2, g_x2);
    cudaGetSymbolAddress((void**)&w2, g_w2);
    cudaGetSymbolAddress((void**)&qb, g_qb);
    cudaGetSymbolAddress((void**)&kb, g_kb);
    cudaGetSymbolAddress((void**)&vb, g_vb);

    cudaFuncSetAttribute(tgemm_kernel<0>, cudaFuncAttributeMaxDynamicSharedMemorySize, SM_TOTAL);
    cudaFuncSetAttribute(tgemm_kernel<1>, cudaFuncAttributeMaxDynamicSharedMemorySize, SM_TOTAL);
    cudaFuncSetAttribute(tgemm_kernel<2>, cudaFuncAttributeMaxDynamicSharedMemorySize, SM_TOTAL);
    cudaFuncSetAttribute(tgemm_kernel<3>, cudaFuncAttributeMaxDynamicSharedMemorySize, SM_TOTAL);
    cudaFuncSetAttribute(fmha_kernel, cudaFuncAttributeMaxDynamicSharedMemorySize, SMF_TOTAL);

    const dim3 gt(8, 64);
    const uint4* x4 = (const uint4*)x2;
    const uint4* w4 = (const uint4*)w2;

    // --- projections ---
    convx_kernel<<<4096, 256>>>(Qin, x2);
    convw_kernel<<<512, 256>>>(wq_r, wq_i, w2);
    tgemm_kernel<0><<<gt, 256, SM_TOTAL>>>(x4, w4, nullptr, nullptr, qb, nullptr);
    convx_kernel<<<4096, 256>>>(Kin, x2);
    convw_kernel<<<512, 256>>>(wk_r, wk_i, w2);
    tgemm_kernel<1><<<gt, 256, SM_TOTAL>>>(x4, w4, nullptr, nullptr, nullptr, kb);
    convx_kernel<<<4096, 256>>>(Vin, x2);
    convw_kernel<<<512, 256>>>(wv_r, wv_i, w2);
    tgemm_kernel<2><<<gt, 256, SM_TOTAL>>>(x4, w4, vr, vi, nullptr, nullptr);
    vconv_kernel<<<dim3(16, 64), 256>>>(vr, vi, vb);

    // --- fused attention (register-resident P) ---
    fmha_kernel<<<dim3(8, 64), 256, SMF_TOTAL>>>(
        (const uint4*)qb, (const uint4*)kb, (const uint4*)vb, o);

    // --- output projection ---
    convx_kernel<<<4096, 256>>>(o, x2);
    convw_kernel<<<512, 256>>>(wo_r, wo_i, w2);
    tgemm_kernel<3><<<gt, 256, SM_TOTAL>>>(x4, w4, (float*)d_out, nullptr, nullptr, nullptr);
}